// round 1
// baseline (speedup 1.0000x reference)
#include <cuda_runtime.h>
#include <math.h>

#define EPSBN 1e-5f

// ---------------- scratch (static device globals; no allocation) ----------------
__device__ float d_t1 [8192 * 64];
__device__ float d_t2 [8192 * 256];
__device__ float d_h  [8192 * 256];
__device__ int   d_gidx[8192 * 8];
__device__ float d_PgA[8192 * 512];
__device__ float d_PcA[8192 * 512];
__device__ float d_UA [65536 * 512];
__device__ float d_l0 [8192 * 512];
__device__ float d_PgB[8192 * 1024];
__device__ float d_PcB[8192 * 1024];
__device__ float d_UB [67108864];          // 65536 * 1024

__device__ float d_sum  [6][1024];
__device__ float d_ssq  [6][1024];
__device__ float d_scale[6][1024];
__device__ float d_shift[6][1024];

// ---------------- init: zero stat accumulators ----------------
__global__ void k_init_stats() {
    int t = blockIdx.x * blockDim.x + threadIdx.x;
    if (t < 6 * 1024) {
        (&d_sum[0][0])[t] = 0.0f;
        (&d_ssq[0][0])[t] = 0.0f;
    }
}

// ---------------- t1 = xyz @ W1^T  (8192x64, K=3) + stats stage0 ----------------
__global__ void k_t1(const float* __restrict__ xyz, const float* __restrict__ W1) {
    __shared__ float w[64][3];
    __shared__ float shs[4][64], shq[4][64];
    int t = threadIdx.x;
    int ch = t & 63, rg = t >> 6;
    if (t < 192) (&w[0][0])[t] = W1[t];
    __syncthreads();
    int r0 = blockIdx.x * 32 + rg * 8;
    float w0 = w[ch][0], w1 = w[ch][1], w2 = w[ch][2];
    float s = 0.0f, q = 0.0f;
#pragma unroll
    for (int i = 0; i < 8; i++) {
        int r = r0 + i;
        float x = xyz[r * 3 + 0], y = xyz[r * 3 + 1], z = xyz[r * 3 + 2];
        float v = fmaf(z, w2, fmaf(y, w1, x * w0));
        d_t1[r * 64 + ch] = v;
        s += v; q = fmaf(v, v, q);
    }
    shs[rg][ch] = s; shq[rg][ch] = q;
    __syncthreads();
    if (rg == 0) {
        s = shs[0][ch] + shs[1][ch] + shs[2][ch] + shs[3][ch];
        q = shq[0][ch] + shq[1][ch] + shq[2][ch] + shq[3][ch];
        atomicAdd(&d_sum[0][ch], s);
        atomicAdd(&d_ssq[0][ch], q);
    }
}

// ---------------- finalize BN stats -> scale/shift ----------------
__global__ void k_finalize(int stage, int C, float count,
                           const float* __restrict__ g, const float* __restrict__ b) {
    int c = blockIdx.x * blockDim.x + threadIdx.x;
    if (c < C) {
        float m = d_sum[stage][c] / count;
        float v = d_ssq[stage][c] / count - m * m;
        float s = g[c] / sqrtf(v + EPSBN);
        d_scale[stage][c] = s;
        d_shift[stage][c] = fmaf(-m, s, b[c]);
    }
}

// ---------------- main tiled GEMM: C[M,N] = Arows @ W^T ----------------
// AMODE 0: A plain.  AMODE 2: bn_relu(A) with scale/shift (per K-channel).
// AMODE 1: row r built as bn_relu(Pg[gidx[r]] + Pc[r>>3]) (gather-combine).
// WSUB: weight = W - Wsub.  STATS: epilogue accumulates per-column sum/sumsq into stage.
template<int AMODE, bool WSUB, bool STATS>
__global__ void __launch_bounds__(256, 2) k_gemm(
    const float* __restrict__ A,
    const float* __restrict__ Pg,
    const float* __restrict__ Pc,
    const float* __restrict__ scale,
    const float* __restrict__ shift,
    const float* __restrict__ W,
    const float* __restrict__ Wsub,
    int ldw,
    float* __restrict__ Cout,
    int N, int K, int stage)
{
    __shared__ __align__(16) float As[8][132];
    __shared__ __align__(16) float Bs[8][132];
    __shared__ int   grs[128];
    __shared__ float colS[128];
    __shared__ float colQ[128];

    const int t = threadIdx.x;
    const int m0 = blockIdx.y * 128;
    const int n0 = blockIdx.x * 128;
    const int lrow = t >> 1;
    const int lc4  = (t & 1) * 4;
    const int rb = (t >> 4) * 8;
    const int cb = (t & 15) * 8;

    if (AMODE == 1) {
        if (t < 128) grs[t] = d_gidx[m0 + t];
        __syncthreads();
    }

    float acc[8][8];
#pragma unroll
    for (int i = 0; i < 8; i++)
#pragma unroll
        for (int j = 0; j < 8; j++) acc[i][j] = 0.0f;

    for (int k0 = 0; k0 < K; k0 += 8) {
        float4 av;
        if (AMODE == 0) {
            av = *(const float4*)(A + (size_t)(m0 + lrow) * K + k0 + lc4);
        } else if (AMODE == 2) {
            float4 r4 = *(const float4*)(A + (size_t)(m0 + lrow) * K + k0 + lc4);
            av.x = fmaxf(fmaf(r4.x, scale[k0 + lc4 + 0], shift[k0 + lc4 + 0]), 0.0f);
            av.y = fmaxf(fmaf(r4.y, scale[k0 + lc4 + 1], shift[k0 + lc4 + 1]), 0.0f);
            av.z = fmaxf(fmaf(r4.z, scale[k0 + lc4 + 2], shift[k0 + lc4 + 2]), 0.0f);
            av.w = fmaxf(fmaf(r4.w, scale[k0 + lc4 + 3], shift[k0 + lc4 + 3]), 0.0f);
        } else {
            const int gr = grs[lrow];
            const int cr = (m0 + lrow) >> 3;
            float4 g4 = *(const float4*)(Pg + (size_t)gr * K + k0 + lc4);
            float4 c4 = *(const float4*)(Pc + (size_t)cr * K + k0 + lc4);
            av.x = fmaxf(fmaf(g4.x + c4.x, scale[k0 + lc4 + 0], shift[k0 + lc4 + 0]), 0.0f);
            av.y = fmaxf(fmaf(g4.y + c4.y, scale[k0 + lc4 + 1], shift[k0 + lc4 + 1]), 0.0f);
            av.z = fmaxf(fmaf(g4.z + c4.z, scale[k0 + lc4 + 2], shift[k0 + lc4 + 2]), 0.0f);
            av.w = fmaxf(fmaf(g4.w + c4.w, scale[k0 + lc4 + 3], shift[k0 + lc4 + 3]), 0.0f);
        }
        float4 wv = *(const float4*)(W + (size_t)(n0 + lrow) * ldw + k0 + lc4);
        if (WSUB) {
            float4 ws = *(const float4*)(Wsub + (size_t)(n0 + lrow) * ldw + k0 + lc4);
            wv.x -= ws.x; wv.y -= ws.y; wv.z -= ws.z; wv.w -= ws.w;
        }
        __syncthreads();
        As[lc4 + 0][lrow] = av.x; As[lc4 + 1][lrow] = av.y;
        As[lc4 + 2][lrow] = av.z; As[lc4 + 3][lrow] = av.w;
        Bs[lc4 + 0][lrow] = wv.x; Bs[lc4 + 1][lrow] = wv.y;
        Bs[lc4 + 2][lrow] = wv.z; Bs[lc4 + 3][lrow] = wv.w;
        __syncthreads();
#pragma unroll
        for (int kk = 0; kk < 8; kk++) {
            float4 a0 = *(const float4*)&As[kk][rb];
            float4 a1 = *(const float4*)&As[kk][rb + 4];
            float4 b0 = *(const float4*)&Bs[kk][cb];
            float4 b1 = *(const float4*)&Bs[kk][cb + 4];
            float ar[8] = {a0.x, a0.y, a0.z, a0.w, a1.x, a1.y, a1.z, a1.w};
            float br[8] = {b0.x, b0.y, b0.z, b0.w, b1.x, b1.y, b1.z, b1.w};
#pragma unroll
            for (int i = 0; i < 8; i++)
#pragma unroll
                for (int j = 0; j < 8; j++)
                    acc[i][j] = fmaf(ar[i], br[j], acc[i][j]);
        }
    }

#pragma unroll
    for (int i = 0; i < 8; i++) {
        float4 v0 = make_float4(acc[i][0], acc[i][1], acc[i][2], acc[i][3]);
        float4 v1 = make_float4(acc[i][4], acc[i][5], acc[i][6], acc[i][7]);
        float* cp = Cout + (size_t)(m0 + rb + i) * N + n0 + cb;
        *(float4*)cp = v0;
        *(float4*)(cp + 4) = v1;
    }

    if (STATS) {
        __syncthreads();
        if (t < 128) { colS[t] = 0.0f; colQ[t] = 0.0f; }
        __syncthreads();
#pragma unroll
        for (int j = 0; j < 8; j++) {
            float s = 0.0f, q = 0.0f;
#pragma unroll
            for (int i = 0; i < 8; i++) { float v = acc[i][j]; s += v; q = fmaf(v, v, q); }
            atomicAdd(&colS[cb + j], s);
            atomicAdd(&colQ[cb + j], q);
        }
        __syncthreads();
        if (t < 128) {
            atomicAdd(&d_sum[stage][n0 + t], colS[t]);
            atomicAdd(&d_ssq[stage][n0 + t], colQ[t]);
        }
    }
}

// ---------------- h = bn_relu(t2) elementwise (8192x256) ----------------
__global__ void k_h() {
    int t = blockIdx.x * 256 + threadIdx.x;      // over 524288 float4
    float4 v = ((const float4*)d_t2)[t];
    int c0 = (t * 4) & 255;
    v.x = fmaxf(fmaf(v.x, d_scale[1][c0 + 0], d_shift[1][c0 + 0]), 0.0f);
    v.y = fmaxf(fmaf(v.y, d_scale[1][c0 + 1], d_shift[1][c0 + 1]), 0.0f);
    v.z = fmaxf(fmaf(v.z, d_scale[1][c0 + 2], d_shift[1][c0 + 2]), 0.0f);
    v.w = fmaxf(fmaf(v.w, d_scale[1][c0 + 3], d_shift[1][c0 + 3]), 0.0f);
    ((float4*)d_h)[t] = v;
}

// ---------------- kNN (k=8) on xyz; stores flattened gather indices ----------------
__global__ void k_knn(const float* __restrict__ xyz) {
    __shared__ float sx[1024], sy[1024], sz[1024], sq[1024];
    int b = blockIdx.x >> 2;
    int q0 = (blockIdx.x & 3) * 256;
    int t = threadIdx.x;
    for (int i = t; i < 1024; i += 256) {
        float x = xyz[(b * 1024 + i) * 3 + 0];
        float y = xyz[(b * 1024 + i) * 3 + 1];
        float z = xyz[(b * 1024 + i) * 3 + 2];
        sx[i] = x; sy[i] = y; sz[i] = z;
        sq[i] = fmaf(z, z, fmaf(y, y, x * x));
    }
    __syncthreads();
    int qi = q0 + t;
    float qx = sx[qi], qy = sy[qi], qz = sz[qi], qs = sq[qi];
    float bd[8]; int bi[8];
#pragma unroll
    for (int k = 0; k < 8; k++) { bd[k] = 3.4e38f; bi[k] = 0; }
    for (int m = 0; m < 1024; m++) {
        float dot = fmaf(qz, sz[m], fmaf(qy, sy[m], qx * sx[m]));
        float d = (qs + sq[m]) - 2.0f * dot;
        if (d < bd[7]) {
            // branchless sorted insert; strict '>' => lower index wins ties (matches top_k)
#pragma unroll
            for (int j = 7; j > 0; j--) {
                bool gt  = bd[j] > d;
                bool gtp = bd[j - 1] > d;
                if (gt) {
                    bd[j] = gtp ? bd[j - 1] : d;
                    bi[j] = gtp ? bi[j - 1] : m;
                }
            }
            if (bd[0] > d) { bd[0] = d; bi[0] = m; }
        }
    }
#pragma unroll
    for (int k = 0; k < 8; k++)
        d_gidx[(b * 1024 + qi) * 8 + k] = b * 1024 + bi[k];
}

// ---------------- stats of u = Pg[gidx[r]] + Pc[r>>3] over 65536 rows ----------------
__global__ void k_stats_u(const float* __restrict__ Pg, const float* __restrict__ Pc,
                          int Cn, int stage) {
    int t = threadIdx.x;
    int r0 = blockIdx.x * 64;
    float accS[4] = {0, 0, 0, 0}, accQ[4] = {0, 0, 0, 0};
    for (int i = 0; i < 64; i++) {
        int r = r0 + i;
        const float* pg = Pg + (size_t)d_gidx[r] * Cn;
        const float* pc = Pc + (size_t)(r >> 3) * Cn;
#pragma unroll
        for (int j = 0; j < 4; j++) {
            int c = t + j * 256;
            if (c < Cn) {
                float v = pg[c] + pc[c];
                accS[j] += v;
                accQ[j] = fmaf(v, v, accQ[j]);
            }
        }
    }
#pragma unroll
    for (int j = 0; j < 4; j++) {
        int c = t + j * 256;
        if (c < Cn) {
            atomicAdd(&d_sum[stage][c], accS[j]);
            atomicAdd(&d_ssq[stage][c], accQ[j]);
        }
    }
}

// ---------------- l0 = max_k bn_relu(UA)  (8192x512) ----------------
__global__ void k_maxA() {
    int t = blockIdx.x * 256 + threadIdx.x;   // over 8192*128 float4
    int p = t >> 7;
    int c = (t & 127) * 4;
    float4 s4 = *(const float4*)&d_scale[3][c];
    float4 h4 = *(const float4*)&d_shift[3][c];
    float4 r; r.x = r.y = r.z = r.w = 0.0f;   // relu output >= 0
#pragma unroll
    for (int k = 0; k < 8; k++) {
        float4 v = *(const float4*)(d_UA + (size_t)(p * 8 + k) * 512 + c);
        r.x = fmaxf(r.x, fmaf(v.x, s4.x, h4.x));
        r.y = fmaxf(r.y, fmaf(v.y, s4.y, h4.y));
        r.z = fmaxf(r.z, fmaf(v.z, s4.z, h4.z));
        r.w = fmaxf(r.w, fmaf(v.w, s4.w, h4.w));
    }
    *(float4*)(d_l0 + (size_t)p * 512 + c) = r;
}

// ---------------- out[b,o,n] = max_k bn_relu(UB[b,n,k,o])  (transposed) ----------------
__global__ void k_maxB_t(float* __restrict__ out) {
    __shared__ float tile[32][33];
    int b = blockIdx.z;
    int o0 = blockIdx.x * 32;
    int n0 = blockIdx.y * 32;
    int tx = threadIdx.x, ty = threadIdx.y;
    float sc = d_scale[5][o0 + tx];
    float sh = d_shift[5][o0 + tx];
#pragma unroll
    for (int jj = 0; jj < 4; jj++) {
        int nl = ty + jj * 8;
        size_t rbase = (size_t)(b * 1024 + n0 + nl) * 8;
        float r = 0.0f;
#pragma unroll
        for (int k = 0; k < 8; k++) {
            float v = d_UB[(rbase + k) * 1024 + o0 + tx];
            r = fmaxf(r, fmaf(v, sc, sh));
        }
        tile[tx][nl] = r;
    }
    __syncthreads();
#pragma unroll
    for (int jj = 0; jj < 4; jj++) {
        int ol = ty + jj * 8;
        out[((size_t)(b * 1024) + o0 + ol) * 1024 + n0 + tx] = tile[ol][tx];
    }
}

// ================= host launcher =================
extern "C" void kernel_launch(void* const* d_in, const int* in_sizes, int n_in,
                              void* d_out, int out_size) {
    const float* xyz = (const float*)d_in[0];
    const float* W1  = (const float*)d_in[1];
    const float* g1  = (const float*)d_in[2];
    const float* b1  = (const float*)d_in[3];
    const float* W2  = (const float*)d_in[4];
    const float* g2  = (const float*)d_in[5];
    const float* b2  = (const float*)d_in[6];
    const float* WA1 = (const float*)d_in[7];
    const float* gA1 = (const float*)d_in[8];
    const float* bA1 = (const float*)d_in[9];
    const float* WA2 = (const float*)d_in[10];
    const float* gA2 = (const float*)d_in[11];
    const float* bA2 = (const float*)d_in[12];
    const float* WB1 = (const float*)d_in[13];
    const float* gB1 = (const float*)d_in[14];
    const float* bB1 = (const float*)d_in[15];
    const float* WB2 = (const float*)d_in[16];
    const float* gB2 = (const float*)d_in[17];
    const float* bB2 = (const float*)d_in[18];

    float *pt1, *pt2, *ph, *pPgA, *pPcA, *pUA, *pl0, *pPgB, *pPcB, *pUB;
    float *pScale, *pShift;
    cudaGetSymbolAddress((void**)&pt1,  d_t1);
    cudaGetSymbolAddress((void**)&pt2,  d_t2);
    cudaGetSymbolAddress((void**)&ph,   d_h);
    cudaGetSymbolAddress((void**)&pPgA, d_PgA);
    cudaGetSymbolAddress((void**)&pPcA, d_PcA);
    cudaGetSymbolAddress((void**)&pUA,  d_UA);
    cudaGetSymbolAddress((void**)&pl0,  d_l0);
    cudaGetSymbolAddress((void**)&pPgB, d_PgB);
    cudaGetSymbolAddress((void**)&pPcB, d_PcB);
    cudaGetSymbolAddress((void**)&pUB,  d_UB);
    cudaGetSymbolAddress((void**)&pScale, d_scale);
    cudaGetSymbolAddress((void**)&pShift, d_shift);

    k_init_stats<<<24, 256>>>();

    // MLP stage 1: t1 + stats0 -> scale0
    k_t1<<<256, 256>>>(xyz, W1);
    k_finalize<<<1, 64>>>(0, 64, 8192.0f, g1, b1);

    // MLP stage 2: t2 = bn_relu(t1) @ W2^T  (+stats1)
    k_gemm<2, false, true><<<dim3(2, 64), 256>>>(
        pt1, nullptr, nullptr, pScale + 0 * 1024, pShift + 0 * 1024,
        W2, nullptr, 64, pt2, 256, 64, 1);
    k_finalize<<<1, 256>>>(1, 256, 8192.0f, g2, b2);
    k_h<<<2048, 256>>>();

    // kNN
    k_knn<<<32, 256>>>(xyz);

    // local_op A, layer 1 factored: PgA = h @ WA1g^T ; PcA = h @ (WA1c-WA1g)^T
    k_gemm<0, false, false><<<dim3(4, 64), 256>>>(
        ph, nullptr, nullptr, nullptr, nullptr, WA1, nullptr, 512, pPgA, 512, 256, 0);
    k_gemm<0, true, false><<<dim3(4, 64), 256>>>(
        ph, nullptr, nullptr, nullptr, nullptr, WA1 + 256, WA1, 512, pPcA, 512, 256, 0);
    k_stats_u<<<1024, 256>>>(pPgA, pPcA, 512, 2);
    k_finalize<<<2, 256>>>(2, 512, 65536.0f, gA1, bA1);

    // local_op A, layer 2: UA = bn_relu(gather(PgA)+PcA) @ WA2^T (+stats3)
    k_gemm<1, false, true><<<dim3(4, 512), 256>>>(
        nullptr, pPgA, pPcA, pScale + 2 * 1024, pShift + 2 * 1024,
        WA2, nullptr, 512, pUA, 512, 512, 3);
    k_finalize<<<2, 256>>>(3, 512, 65536.0f, gA2, bA2);
    k_maxA<<<4096, 256>>>();

    // local_op B, layer 1 factored
    k_gemm<0, false, false><<<dim3(8, 64), 256>>>(
        pl0, nullptr, nullptr, nullptr, nullptr, WB1, nullptr, 1024, pPgB, 1024, 512, 0);
    k_gemm<0, true, false><<<dim3(8, 64), 256>>>(
        pl0, nullptr, nullptr, nullptr, nullptr, WB1 + 512, WB1, 1024, pPcB, 1024, 512, 0);
    k_stats_u<<<1024, 256>>>(pPgB, pPcB, 1024, 4);
    k_finalize<<<4, 256>>>(4, 1024, 65536.0f, gB1, bB1);

    // local_op B, layer 2 (dominant GEMM, 137 GF)
    k_gemm<1, false, true><<<dim3(8, 512), 256>>>(
        nullptr, pPgB, pPcB, pScale + 4 * 1024, pShift + 4 * 1024,
        WB2, nullptr, 1024, pUB, 1024, 1024, 5);
    k_finalize<<<4, 256>>>(5, 1024, 65536.0f, gB2, bB2);

    // maxpool over k + bn_relu + transpose to (B, C, N)
    k_maxB_t<<<dim3(32, 32, 8), dim3(32, 8)>>>((float*)d_out);
}

// round 4
// speedup vs baseline: 1.7149x; 1.7149x over previous
#include <cuda_runtime.h>
#include <cuda_fp16.h>
#include <math.h>
#include <stdint.h>

#define EPSBN 1e-5f

// ---------------- scratch (static device globals; no allocation) ----------------
__device__ float d_t1 [8192 * 64];
__device__ float d_t2 [8192 * 256];
__device__ float d_h  [8192 * 256];
__device__ int   d_gidx[8192 * 8];
__device__ float d_PgA[8192 * 512];
__device__ float d_PcA[8192 * 512];
__device__ float d_UA [65536 * 512];
__device__ float d_l0 [8192 * 512];
__device__ float d_PgB[8192 * 1024];
__device__ float d_PcB[8192 * 1024];
__device__ float d_UB [67108864];          // 65536 * 1024

__device__ float d_sum  [6][1024];
__device__ float d_ssq  [6][1024];
__device__ float d_scale[6][1024];
__device__ float d_shift[6][1024];

__device__ __forceinline__ uint32_t smem_u32(const void* p) {
    uint32_t a;
    asm("{ .reg .u64 t; cvta.to.shared.u64 t, %1; cvt.u32.u64 %0, t; }" : "=r"(a) : "l"(p));
    return a;
}
// split (a,b) into hi fp16 pair and lo (residual) fp16 pair
__device__ __forceinline__ void f2h2_split(float a, float b, uint32_t& hi, uint32_t& lo) {
    __half2 h = __floats2half2_rn(a, b);
    float2 hf = __half22float2(h);
    __half2 l = __floats2half2_rn(a - hf.x, b - hf.y);
    hi = *reinterpret_cast<uint32_t*>(&h);
    lo = *reinterpret_cast<uint32_t*>(&l);
}

// ---------------- init: zero stat accumulators ----------------
__global__ void k_init_stats() {
    int t = blockIdx.x * blockDim.x + threadIdx.x;
    if (t < 6 * 1024) {
        (&d_sum[0][0])[t] = 0.0f;
        (&d_ssq[0][0])[t] = 0.0f;
    }
}

// ---------------- t1 = xyz @ W1^T  (8192x64, K=3) + stats stage0 ----------------
__global__ void k_t1(const float* __restrict__ xyz, const float* __restrict__ W1) {
    __shared__ float w[64][3];
    __shared__ float shs[4][64], shq[4][64];
    int t = threadIdx.x;
    int ch = t & 63, rg = t >> 6;
    if (t < 192) (&w[0][0])[t] = W1[t];
    __syncthreads();
    int r0 = blockIdx.x * 32 + rg * 8;
    float w0 = w[ch][0], w1 = w[ch][1], w2 = w[ch][2];
    float s = 0.0f, q = 0.0f;
#pragma unroll
    for (int i = 0; i < 8; i++) {
        int r = r0 + i;
        float x = xyz[r * 3 + 0], y = xyz[r * 3 + 1], z = xyz[r * 3 + 2];
        float v = fmaf(z, w2, fmaf(y, w1, x * w0));
        d_t1[r * 64 + ch] = v;
        s += v; q = fmaf(v, v, q);
    }
    shs[rg][ch] = s; shq[rg][ch] = q;
    __syncthreads();
    if (rg == 0) {
        s = shs[0][ch] + shs[1][ch] + shs[2][ch] + shs[3][ch];
        q = shq[0][ch] + shq[1][ch] + shq[2][ch] + shq[3][ch];
        atomicAdd(&d_sum[0][ch], s);
        atomicAdd(&d_ssq[0][ch], q);
    }
}

// ---------------- finalize BN stats -> scale/shift ----------------
__global__ void k_finalize(int stage, int C, float count,
                           const float* __restrict__ g, const float* __restrict__ b) {
    int c = blockIdx.x * blockDim.x + threadIdx.x;
    if (c < C) {
        float m = d_sum[stage][c] / count;
        float v = d_ssq[stage][c] / count - m * m;
        float s = g[c] / sqrtf(v + EPSBN);
        d_scale[stage][c] = s;
        d_shift[stage][c] = fmaf(-m, s, b[c]);
    }
}

// ================= split-precision fp16 mma GEMM: C[M,N] = Arows @ W^T =================
// BM=128, BN=128, BK=32. 256 threads = 8 warps (2 x 4), warp tile 64x32.
// Each operand split x = xh + xl (fp16 pair). C = Ah*Bh + Ah*Bl + Al*Bh, fp32 accum.
// Double-buffered smem: per stage {Ah, Al, Bh, Bl} tiles, 80B row stride.
// AMODE 0: A plain. AMODE 2: bn_relu(A). AMODE 1: bn_relu(Pg[gidx[r]] + Pc[r>>3]).

static constexpr int LDSH = 40;                        // halves per smem row (80B)
static constexpr int TILE_B = 128 * LDSH * 2;          // 10240 bytes per tile
static constexpr int STAGE_B = 4 * TILE_B;             // Ah,Al,Bh,Bl
static constexpr int GSMEM = 2 * STAGE_B;              // 81920 bytes

template<int AMODE, bool WSUB>
__device__ __forceinline__ void fetch_tiles(
    uint2 ah[4], uint2 al[4], uint2 wh[4], uint2 wl[4],
    const float* __restrict__ A, const float* __restrict__ Pg, const float* __restrict__ Pc,
    const float* __restrict__ scale, const float* __restrict__ shift,
    const float* __restrict__ W, const float* __restrict__ Wsub, int ldw,
    const int* grs, int m0, int n0, int K, int k0, int t)
{
#pragma unroll
    for (int i = 0; i < 4; i++) {
        int cid = t + i * 256;
        int r = cid >> 3;
        int c = k0 + (cid & 7) * 4;
        float4 v;
        if (AMODE == 0) {
            v = *(const float4*)(A + (size_t)(m0 + r) * K + c);
        } else if (AMODE == 2) {
            float4 x = *(const float4*)(A + (size_t)(m0 + r) * K + c);
            float4 s4 = *(const float4*)(scale + c);
            float4 h4 = *(const float4*)(shift + c);
            v.x = fmaxf(fmaf(x.x, s4.x, h4.x), 0.0f);
            v.y = fmaxf(fmaf(x.y, s4.y, h4.y), 0.0f);
            v.z = fmaxf(fmaf(x.z, s4.z, h4.z), 0.0f);
            v.w = fmaxf(fmaf(x.w, s4.w, h4.w), 0.0f);
        } else {
            float4 g4 = *(const float4*)(Pg + (size_t)grs[r] * K + c);
            float4 c4 = *(const float4*)(Pc + (size_t)((m0 + r) >> 3) * K + c);
            float4 s4 = *(const float4*)(scale + c);
            float4 h4 = *(const float4*)(shift + c);
            v.x = fmaxf(fmaf(g4.x + c4.x, s4.x, h4.x), 0.0f);
            v.y = fmaxf(fmaf(g4.y + c4.y, s4.y, h4.y), 0.0f);
            v.z = fmaxf(fmaf(g4.z + c4.z, s4.z, h4.z), 0.0f);
            v.w = fmaxf(fmaf(g4.w + c4.w, s4.w, h4.w), 0.0f);
        }
        f2h2_split(v.x, v.y, ah[i].x, al[i].x);
        f2h2_split(v.z, v.w, ah[i].y, al[i].y);

        float4 w4 = *(const float4*)(W + (size_t)(n0 + r) * ldw + c);
        if (WSUB) {
            float4 u4 = *(const float4*)(Wsub + (size_t)(n0 + r) * ldw + c);
            w4.x -= u4.x; w4.y -= u4.y; w4.z -= u4.z; w4.w -= u4.w;
        }
        f2h2_split(w4.x, w4.y, wh[i].x, wl[i].x);
        f2h2_split(w4.z, w4.w, wh[i].y, wl[i].y);
    }
}

__device__ __forceinline__ void store_stage(char* base, int t, int i,
                                            uint2 ah, uint2 al, uint2 wh, uint2 wl) {
    int cid = t + i * 256;
    int off = ((cid >> 3) * LDSH + (cid & 7) * 4) * 2;
    *(uint2*)(base + 0 * TILE_B + off) = ah;
    *(uint2*)(base + 1 * TILE_B + off) = al;
    *(uint2*)(base + 2 * TILE_B + off) = wh;
    *(uint2*)(base + 3 * TILE_B + off) = wl;
}

#define MMA_16816(ACC, AF, B0, B1)                                              \
    asm volatile(                                                               \
        "mma.sync.aligned.m16n8k16.row.col.f32.f16.f16.f32 "                    \
        "{%0,%1,%2,%3}, {%4,%5,%6,%7}, {%8,%9}, {%0,%1,%2,%3};"                 \
        : "+f"(ACC[0]), "+f"(ACC[1]), "+f"(ACC[2]), "+f"(ACC[3])                \
        : "r"(AF[0]), "r"(AF[1]), "r"(AF[2]), "r"(AF[3]), "r"(B0), "r"(B1))

template<int AMODE, bool WSUB>
__global__ void __launch_bounds__(256) k_gemm_mma(
    const float* __restrict__ A,
    const float* __restrict__ Pg,
    const float* __restrict__ Pc,
    const float* __restrict__ scale,
    const float* __restrict__ shift,
    const float* __restrict__ W,
    const float* __restrict__ Wsub,
    int ldw,
    float* __restrict__ Cout,
    int N, int K)
{
    extern __shared__ __align__(16) char sm[];
    __shared__ int grs[128];

    const int t = threadIdx.x;
    const int m0 = blockIdx.y * 128;
    const int n0 = blockIdx.x * 128;
    const int lane = t & 31;
    const int wid = t >> 5;
    const int mw = (wid >> 2) * 64;
    const int nw = (wid & 3) * 32;

    if (AMODE == 1) {
        if (t < 128) grs[t] = d_gidx[m0 + t];
        __syncthreads();
    }

    float acc[4][4][4];
#pragma unroll
    for (int a = 0; a < 4; a++)
#pragma unroll
        for (int b = 0; b < 4; b++)
#pragma unroll
            for (int cidx = 0; cidx < 4; cidx++) acc[a][b][cidx] = 0.0f;

    const uint32_t sBase = smem_u32(sm);

    uint2 ah[4], al[4], wh[4], wl[4];
    fetch_tiles<AMODE, WSUB>(ah, al, wh, wl, A, Pg, Pc, scale, shift, W, Wsub, ldw,
                             grs, m0, n0, K, 0, t);
#pragma unroll
    for (int i = 0; i < 4; i++) store_stage(sm, t, i, ah[i], al[i], wh[i], wl[i]);
    __syncthreads();

    const int lrow = ((lane >> 3) & 1) * 8 + (lane & 7);
    const int lcol = (lane >> 4) * 8;

    const int nch = K >> 5;
    for (int it = 0; it < nch; ++it) {
        const int s = it & 1;
        if (it + 1 < nch)
            fetch_tiles<AMODE, WSUB>(ah, al, wh, wl, A, Pg, Pc, scale, shift, W, Wsub, ldw,
                                     grs, m0, n0, K, (it + 1) << 5, t);
        const uint32_t stg = sBase + s * STAGE_B;
#pragma unroll
        for (int ks = 0; ks < 2; ks++) {
            const int k0 = ks * 16;
            uint32_t afh[4][4], afl[4][4];
#pragma unroll
            for (int mt = 0; mt < 4; mt++) {
                uint32_t addr = stg + ((mw + mt * 16 + lrow) * LDSH + k0 + lcol) * 2;
                asm volatile("ldmatrix.sync.aligned.m8n8.x4.shared.b16 {%0,%1,%2,%3}, [%4];"
                             : "=r"(afh[mt][0]), "=r"(afh[mt][1]), "=r"(afh[mt][2]), "=r"(afh[mt][3])
                             : "r"(addr));
                asm volatile("ldmatrix.sync.aligned.m8n8.x4.shared.b16 {%0,%1,%2,%3}, [%4];"
                             : "=r"(afl[mt][0]), "=r"(afl[mt][1]), "=r"(afl[mt][2]), "=r"(afl[mt][3])
                             : "r"(addr + TILE_B));
            }
            uint32_t bfh[4][2], bfl[4][2];
#pragma unroll
            for (int nt = 0; nt < 4; nt++) {
                const char* bp = sm + s * STAGE_B + 2 * TILE_B +
                    ((nw + nt * 8 + (lane >> 2)) * LDSH + k0 + 2 * (lane & 3)) * 2;
                bfh[nt][0] = *(const uint32_t*)bp;
                bfh[nt][1] = *(const uint32_t*)(bp + 16);
                bfl[nt][0] = *(const uint32_t*)(bp + TILE_B);
                bfl[nt][1] = *(const uint32_t*)(bp + TILE_B + 16);
            }
#pragma unroll
            for (int mt = 0; mt < 4; mt++)
#pragma unroll
                for (int nt = 0; nt < 4; nt++) {
                    MMA_16816(acc[mt][nt], afh[mt], bfh[nt][0], bfh[nt][1]);
                    MMA_16816(acc[mt][nt], afh[mt], bfl[nt][0], bfl[nt][1]);
                    MMA_16816(acc[mt][nt], afl[mt], bfh[nt][0], bfh[nt][1]);
                }
        }
        if (it + 1 < nch) {
            char* nb = sm + ((it + 1) & 1) * STAGE_B;
            __syncthreads();
#pragma unroll
            for (int i = 0; i < 4; i++) store_stage(nb, t, i, ah[i], al[i], wh[i], wl[i]);
            __syncthreads();
        }
    }

    // epilogue: fp32 accumulators -> global
#pragma unroll
    for (int mt = 0; mt < 4; mt++) {
        int r0 = m0 + mw + mt * 16 + (lane >> 2);
#pragma unroll
        for (int nt = 0; nt < 4; nt++) {
            int c = n0 + nw + nt * 8 + 2 * (lane & 3);
            *(float2*)&Cout[(size_t)r0 * N + c] =
                make_float2(acc[mt][nt][0], acc[mt][nt][1]);
            *(float2*)&Cout[(size_t)(r0 + 8) * N + c] =
                make_float2(acc[mt][nt][2], acc[mt][nt][3]);
        }
    }
}

// ---------------- h = bn_relu(t2) elementwise (8192x256) ----------------
__global__ void k_h() {
    int t = blockIdx.x * 256 + threadIdx.x;
    float4 v = ((const float4*)d_t2)[t];
    int c0 = (t * 4) & 255;
    v.x = fmaxf(fmaf(v.x, d_scale[1][c0 + 0], d_shift[1][c0 + 0]), 0.0f);
    v.y = fmaxf(fmaf(v.y, d_scale[1][c0 + 1], d_shift[1][c0 + 1]), 0.0f);
    v.z = fmaxf(fmaf(v.z, d_scale[1][c0 + 2], d_shift[1][c0 + 2]), 0.0f);
    v.w = fmaxf(fmaf(v.w, d_scale[1][c0 + 3], d_shift[1][c0 + 3]), 0.0f);
    ((float4*)d_h)[t] = v;
}

// ---------------- kNN (k=8) on xyz ----------------
__global__ void k_knn(const float* __restrict__ xyz) {
    __shared__ float sx[1024], sy[1024], sz[1024], sq[1024];
    int b = blockIdx.x >> 2;
    int q0 = (blockIdx.x & 3) * 256;
    int t = threadIdx.x;
    for (int i = t; i < 1024; i += 256) {
        float x = xyz[(b * 1024 + i) * 3 + 0];
        float y = xyz[(b * 1024 + i) * 3 + 1];
        float z = xyz[(b * 1024 + i) * 3 + 2];
        sx[i] = x; sy[i] = y; sz[i] = z;
        sq[i] = fmaf(z, z, fmaf(y, y, x * x));
    }
    __syncthreads();
    int qi = q0 + t;
    float qx = sx[qi], qy = sy[qi], qz = sz[qi], qs = sq[qi];
    float bd[8]; int bi[8];
#pragma unroll
    for (int k = 0; k < 8; k++) { bd[k] = 3.4e38f; bi[k] = 0; }
    for (int m = 0; m < 1024; m++) {
        float dot = fmaf(qz, sz[m], fmaf(qy, sy[m], qx * sx[m]));
        float d = (qs + sq[m]) - 2.0f * dot;
        if (d < bd[7]) {
#pragma unroll
            for (int j = 7; j > 0; j--) {
                bool gt  = bd[j] > d;
                bool gtp = bd[j - 1] > d;
                if (gt) {
                    bd[j] = gtp ? bd[j - 1] : d;
                    bi[j] = gtp ? bi[j - 1] : m;
                }
            }
            if (bd[0] > d) { bd[0] = d; bi[0] = m; }
        }
    }
#pragma unroll
    for (int k = 0; k < 8; k++)
        d_gidx[(b * 1024 + qi) * 8 + k] = b * 1024 + bi[k];
}

// ---------------- stats of u = Pg[gidx[r]] + Pc[r>>3] over 65536 rows ----------------
__global__ void k_stats_u(const float* __restrict__ Pg, const float* __restrict__ Pc,
                          int Cn, int stage) {
    int t = threadIdx.x;
    int r0 = blockIdx.x * 64;
    float accS[4] = {0, 0, 0, 0}, accQ[4] = {0, 0, 0, 0};
    for (int i = 0; i < 64; i++) {
        int r = r0 + i;
        const float* pg = Pg + (size_t)d_gidx[r] * Cn;
        const float* pc = Pc + (size_t)(r >> 3) * Cn;
#pragma unroll
        for (int j = 0; j < 4; j++) {
            int c = t + j * 256;
            if (c < Cn) {
                float v = pg[c] + pc[c];
                accS[j] += v;
                accQ[j] = fmaf(v, v, accQ[j]);
            }
        }
    }
#pragma unroll
    for (int j = 0; j < 4; j++) {
        int c = t + j * 256;
        if (c < Cn) {
            atomicAdd(&d_sum[stage][c], accS[j]);
            atomicAdd(&d_ssq[stage][c], accQ[j]);
        }
    }
}

// ---------------- per-column stats of raw matrix X ----------------
__global__ void k_stats_raw(const float* __restrict__ X, int C, int stage) {
    int t = threadIdx.x;
    int r0 = blockIdx.x * 64;
    float aS[4] = {0, 0, 0, 0}, aQ[4] = {0, 0, 0, 0};
    for (int i = 0; i < 64; i++) {
        const float* xr = X + (size_t)(r0 + i) * C;
#pragma unroll
        for (int j = 0; j < 4; j++) {
            int c = t + j * 256;
            if (c < C) {
                float v = xr[c];
                aS[j] += v;
                aQ[j] = fmaf(v, v, aQ[j]);
            }
        }
    }
#pragma unroll
    for (int j = 0; j < 4; j++) {
        int c = t + j * 256;
        if (c < C) {
            atomicAdd(&d_sum[stage][c], aS[j]);
            atomicAdd(&d_ssq[stage][c], aQ[j]);
        }
    }
}

// ---------------- l0 = max_k bn_relu(UA)  (8192x512) ----------------
__global__ void k_maxA() {
    int t = blockIdx.x * 256 + threadIdx.x;
    int p = t >> 7;
    int c = (t & 127) * 4;
    float4 s4 = *(const float4*)&d_scale[3][c];
    float4 h4 = *(const float4*)&d_shift[3][c];
    float4 r; r.x = r.y = r.z = r.w = 0.0f;
#pragma unroll
    for (int k = 0; k < 8; k++) {
        float4 v = *(const float4*)(d_UA + (size_t)(p * 8 + k) * 512 + c);
        r.x = fmaxf(r.x, fmaf(v.x, s4.x, h4.x));
        r.y = fmaxf(r.y, fmaf(v.y, s4.y, h4.y));
        r.z = fmaxf(r.z, fmaf(v.z, s4.z, h4.z));
        r.w = fmaxf(r.w, fmaf(v.w, s4.w, h4.w));
    }
    *(float4*)(d_l0 + (size_t)p * 512 + c) = r;
}

// ---------------- out[b,o,n] = max_k bn_relu(UB[b,n,k,o]) ----------------
__global__ void k_maxB_t(float* __restrict__ out) {
    __shared__ float tile[32][33];
    int b = blockIdx.z;
    int o0 = blockIdx.x * 32;
    int n0 = blockIdx.y * 32;
    int tx = threadIdx.x, ty = threadIdx.y;
    float sc = d_scale[5][o0 + tx];
    float sh = d_shift[5][o0 + tx];
#pragma unroll
    for (int jj = 0; jj < 4; jj++) {
        int nl = ty + jj * 8;
        size_t rbase = (size_t)(b * 1024 + n0 + nl) * 8;
        float r = 0.0f;
#pragma unroll
        for (int k = 0; k < 8; k++) {
            float v = d_UB[(rbase + k) * 1024 + o0 + tx];
            r = fmaxf(r, fmaf(v, sc, sh));
        }
        tile[tx][nl] = r;
    }
    __syncthreads();
#pragma unroll
    for (int jj = 0; jj < 4; jj++) {
        int ol = ty + jj * 8;
        out[((size_t)(b * 1024) + o0 + ol) * 1024 + n0 + tx] = tile[ol][tx];
    }
}

// ================= host launcher =================
extern "C" void kernel_launch(void* const* d_in, const int* in_sizes, int n_in,
                              void* d_out, int out_size) {
    const float* xyz = (const float*)d_in[0];
    const float* W1  = (const float*)d_in[1];
    const float* g1  = (const float*)d_in[2];
    const float* b1  = (const float*)d_in[3];
    const float* W2  = (const float*)d_in[4];
    const float* g2  = (const float*)d_in[5];
    const float* b2  = (const float*)d_in[6];
    const float* WA1 = (const float*)d_in[7];
    const float* gA1 = (const float*)d_in[8];
    const float* bA1 = (const float*)d_in[9];
    const float* WA2 = (const float*)d_in[10];
    const float* gA2 = (const float*)d_in[11];
    const float* bA2 = (const float*)d_in[12];
    const float* WB1 = (const float*)d_in[13];
    const float* gB1 = (const float*)d_in[14];
    const float* bB1 = (const float*)d_in[15];
    const float* WB2 = (const float*)d_in[16];
    const float* gB2 = (const float*)d_in[17];
    const float* bB2 = (const float*)d_in[18];

    float *pt1, *pt2, *ph, *pPgA, *pPcA, *pUA, *pl0, *pPgB, *pPcB, *pUB;
    float *pScale, *pShift;
    cudaGetSymbolAddress((void**)&pt1,  d_t1);
    cudaGetSymbolAddress((void**)&pt2,  d_t2);
    cudaGetSymbolAddress((void**)&ph,   d_h);
    cudaGetSymbolAddress((void**)&pPgA, d_PgA);
    cudaGetSymbolAddress((void**)&pPcA, d_PcA);
    cudaGetSymbolAddress((void**)&pUA,  d_UA);
    cudaGetSymbolAddress((void**)&pl0,  d_l0);
    cudaGetSymbolAddress((void**)&pPgB, d_PgB);
    cudaGetSymbolAddress((void**)&pPcB, d_PcB);
    cudaGetSymbolAddress((void**)&pUB,  d_UB);
    cudaGetSymbolAddress((void**)&pScale, d_scale);
    cudaGetSymbolAddress((void**)&pShift, d_shift);

    cudaFuncSetAttribute(k_gemm_mma<0, false>, cudaFuncAttributeMaxDynamicSharedMemorySize, GSMEM);
    cudaFuncSetAttribute(k_gemm_mma<0, true >, cudaFuncAttributeMaxDynamicSharedMemorySize, GSMEM);
    cudaFuncSetAttribute(k_gemm_mma<1, false>, cudaFuncAttributeMaxDynamicSharedMemorySize, GSMEM);
    cudaFuncSetAttribute(k_gemm_mma<2, false>, cudaFuncAttributeMaxDynamicSharedMemorySize, GSMEM);

    k_init_stats<<<24, 256>>>();

    // MLP stage 1: t1 + stats0
    k_t1<<<256, 256>>>(xyz, W1);
    k_finalize<<<1, 64>>>(0, 64, 8192.0f, g1, b1);

    // MLP stage 2: t2 = bn_relu(t1) @ W2^T
    k_gemm_mma<2, false><<<dim3(2, 64), 256, GSMEM>>>(
        pt1, nullptr, nullptr, pScale + 0 * 1024, pShift + 0 * 1024,
        W2, nullptr, 64, pt2, 256, 64);
    k_stats_raw<<<128, 256>>>(pt2, 256, 1);
    k_finalize<<<1, 256>>>(1, 256, 8192.0f, g2, b2);
    k_h<<<2048, 256>>>();

    // kNN
    k_knn<<<32, 256>>>(xyz);

    // local_op A, layer 1 factored: PgA = h @ WA1g^T ; PcA = h @ (WA1c-WA1g)^T
    k_gemm_mma<0, false><<<dim3(4, 64), 256, GSMEM>>>(
        ph, nullptr, nullptr, nullptr, nullptr, WA1, nullptr, 512, pPgA, 512, 256);
    k_gemm_mma<0, true><<<dim3(4, 64), 256, GSMEM>>>(
        ph, nullptr, nullptr, nullptr, nullptr, WA1 + 256, WA1, 512, pPcA, 512, 256);
    k_stats_u<<<1024, 256>>>(pPgA, pPcA, 512, 2);
    k_finalize<<<2, 256>>>(2, 512, 65536.0f, gA1, bA1);

    // local_op A, layer 2
    k_gemm_mma<1, false><<<dim3(4, 512), 256, GSMEM>>>(
        nullptr, pPgA, pPcA, pScale + 2 * 1024, pShift + 2 * 1024,
        WA2, nullptr, 512, pUA, 512, 512);
    k_stats_raw<<<1024, 256>>>(pUA, 512, 3);
    k_finalize<<<2, 256>>>(3, 512, 65536.0f, gA2, bA2);
    k_maxA<<<4096, 256>>>();

    // local_op B, layer 1 factored
    k_gemm_mma<0, false><<<dim3(8, 64), 256, GSMEM>>>(
        pl0, nullptr, nullptr, nullptr, nullptr, WB1, nullptr, 1024, pPgB, 1024, 512);
    k_gemm_mma<0, true><<<dim3(8, 64), 256, GSMEM>>>(
        pl0, nullptr, nullptr, nullptr, nullptr, WB1 + 512, WB1, 1024, pPcB, 1024, 512);
    k_stats_u<<<1024, 256>>>(pPgB, pPcB, 1024, 4);
    k_finalize<<<4, 256>>>(4, 1024, 65536.0f, gB1, bB1);

    // local_op B, layer 2 (dominant GEMM)
    k_gemm_mma<1, false><<<dim3(8, 512), 256, GSMEM>>>(
        nullptr, pPgB, pPcB, pScale + 4 * 1024, pShift + 4 * 1024,
        WB2, nullptr, 1024, pUB, 1024, 1024);
    k_stats_raw<<<1024, 256>>>(pUB, 1024, 5);
    k_finalize<<<4, 256>>>(5, 1024, 65536.0f, gB2, bB2);

    // maxpool over k + bn_relu + transpose
    k_maxB_t<<<dim3(32, 32, 8), dim3(32, 8)>>>((float*)d_out);
}

// round 6
// speedup vs baseline: 1.8391x; 1.0724x over previous
#include <cuda_runtime.h>
#include <cuda_fp16.h>
#include <math.h>
#include <stdint.h>

#define EPSBN 1e-5f

// ---------------- scratch (static device globals; no allocation) ----------------
__device__ float d_t1 [8192 * 64];
__device__ float d_t2 [8192 * 256];
__device__ float d_h  [8192 * 256];
__device__ int   d_gidx[8192 * 8];
__device__ float d_PgA[8192 * 512];
__device__ float d_PcA[8192 * 512];
__device__ float d_maxA[8192 * 512];
__device__ float d_minA[8192 * 512];
__device__ float d_l0 [8192 * 512];
__device__ float d_PgB[8192 * 1024];
__device__ float d_PcB[8192 * 1024];
__device__ float d_maxB[8192 * 1024];
__device__ float d_minB[8192 * 1024];

__device__ float d_sum  [6][1024];
__device__ float d_ssq  [6][1024];
__device__ float d_scale[6][1024];
__device__ float d_shift[6][1024];

__device__ __forceinline__ uint32_t smem_u32(const void* p) {
    uint32_t a;
    asm("{ .reg .u64 t; cvta.to.shared.u64 t, %1; cvt.u32.u64 %0, t; }" : "=r"(a) : "l"(p));
    return a;
}
// split (a,b) into hi fp16 pair and lo (residual) fp16 pair
__device__ __forceinline__ void f2h2_split(float a, float b, uint32_t& hi, uint32_t& lo) {
    __half2 h = __floats2half2_rn(a, b);
    float2 hf = __half22float2(h);
    __half2 l = __floats2half2_rn(a - hf.x, b - hf.y);
    hi = *reinterpret_cast<uint32_t*>(&h);
    lo = *reinterpret_cast<uint32_t*>(&l);
}

// ---------------- init: zero stat accumulators ----------------
__global__ void k_init_stats() {
    int t = blockIdx.x * blockDim.x + threadIdx.x;
    if (t < 6 * 1024) {
        (&d_sum[0][0])[t] = 0.0f;
        (&d_ssq[0][0])[t] = 0.0f;
    }
}

// ---------------- t1 = xyz @ W1^T  (8192x64, K=3) + stats stage0 ----------------
__global__ void k_t1(const float* __restrict__ xyz, const float* __restrict__ W1) {
    __shared__ float w[64][3];
    __shared__ float shs[4][64], shq[4][64];
    int t = threadIdx.x;
    int ch = t & 63, rg = t >> 6;
    if (t < 192) (&w[0][0])[t] = W1[t];
    __syncthreads();
    int r0 = blockIdx.x * 32 + rg * 8;
    float w0 = w[ch][0], w1 = w[ch][1], w2 = w[ch][2];
    float s = 0.0f, q = 0.0f;
#pragma unroll
    for (int i = 0; i < 8; i++) {
        int r = r0 + i;
        float x = xyz[r * 3 + 0], y = xyz[r * 3 + 1], z = xyz[r * 3 + 2];
        float v = fmaf(z, w2, fmaf(y, w1, x * w0));
        d_t1[r * 64 + ch] = v;
        s += v; q = fmaf(v, v, q);
    }
    shs[rg][ch] = s; shq[rg][ch] = q;
    __syncthreads();
    if (rg == 0) {
        s = shs[0][ch] + shs[1][ch] + shs[2][ch] + shs[3][ch];
        q = shq[0][ch] + shq[1][ch] + shq[2][ch] + shq[3][ch];
        atomicAdd(&d_sum[0][ch], s);
        atomicAdd(&d_ssq[0][ch], q);
    }
}

// ---------------- finalize BN stats -> scale/shift ----------------
__global__ void k_finalize(int stage, int C, float count,
                           const float* __restrict__ g, const float* __restrict__ b) {
    int c = blockIdx.x * blockDim.x + threadIdx.x;
    if (c < C) {
        float m = d_sum[stage][c] / count;
        float v = d_ssq[stage][c] / count - m * m;
        float s = g[c] / sqrtf(v + EPSBN);
        d_scale[stage][c] = s;
        d_shift[stage][c] = fmaf(-m, s, b[c]);
    }
}

// ================= split-precision fp16 mma GEMM: C[M,N] = Arows @ W^T =================
// BM=128, BN=128, BK=32. 256 threads = 8 warps (2 x 4), warp tile 64x32.
// Each operand split x = xh + xl (fp16 pair). C = Ah*Bh + Ah*Bl + Al*Bh, fp32 accum.
// Double-buffered smem: per stage {Ah, Al, Bh, Bl} tiles, 80B row stride.
// AMODE 0: A plain. AMODE 2: bn_relu(A). AMODE 1: bn_relu(Pg[gidx[r]] + Pc[r>>3]).
// EPI 0: plain store. EPI 1: store + column stats (stage). EPI 2: no store;
//        per-point max/min over k=8 (rows grouped 8-per-point) + column stats.

static constexpr int LDSH = 40;                        // halves per smem row (80B)
static constexpr int TILE_B = 128 * LDSH * 2;          // 10240 bytes per tile
static constexpr int STAGE_B = 4 * TILE_B;             // Ah,Al,Bh,Bl
static constexpr int GSMEM = 2 * STAGE_B;              // 81920 bytes (>= 128*130*4 scratch)

template<int AMODE, bool WSUB>
__device__ __forceinline__ void fetch_tiles(
    uint2 ah[4], uint2 al[4], uint2 wh[4], uint2 wl[4],
    const float* __restrict__ A, const float* __restrict__ Pg, const float* __restrict__ Pc,
    const float* __restrict__ scale, const float* __restrict__ shift,
    const float* __restrict__ W, const float* __restrict__ Wsub, int ldw,
    const int* grs, int m0, int n0, int K, int k0, int t)
{
#pragma unroll
    for (int i = 0; i < 4; i++) {
        int cid = t + i * 256;
        int r = cid >> 3;
        int c = k0 + (cid & 7) * 4;
        float4 v;
        if (AMODE == 0) {
            v = *(const float4*)(A + (size_t)(m0 + r) * K + c);
        } else if (AMODE == 2) {
            float4 x = *(const float4*)(A + (size_t)(m0 + r) * K + c);
            float4 s4 = *(const float4*)(scale + c);
            float4 h4 = *(const float4*)(shift + c);
            v.x = fmaxf(fmaf(x.x, s4.x, h4.x), 0.0f);
            v.y = fmaxf(fmaf(x.y, s4.y, h4.y), 0.0f);
            v.z = fmaxf(fmaf(x.z, s4.z, h4.z), 0.0f);
            v.w = fmaxf(fmaf(x.w, s4.w, h4.w), 0.0f);
        } else {
            float4 g4 = *(const float4*)(Pg + (size_t)grs[r] * K + c);
            float4 c4 = *(const float4*)(Pc + (size_t)((m0 + r) >> 3) * K + c);
            float4 s4 = *(const float4*)(scale + c);
            float4 h4 = *(const float4*)(shift + c);
            v.x = fmaxf(fmaf(g4.x + c4.x, s4.x, h4.x), 0.0f);
            v.y = fmaxf(fmaf(g4.y + c4.y, s4.y, h4.y), 0.0f);
            v.z = fmaxf(fmaf(g4.z + c4.z, s4.z, h4.z), 0.0f);
            v.w = fmaxf(fmaf(g4.w + c4.w, s4.w, h4.w), 0.0f);
        }
        f2h2_split(v.x, v.y, ah[i].x, al[i].x);
        f2h2_split(v.z, v.w, ah[i].y, al[i].y);

        float4 w4 = *(const float4*)(W + (size_t)(n0 + r) * ldw + c);
        if (WSUB) {
            float4 u4 = *(const float4*)(Wsub + (size_t)(n0 + r) * ldw + c);
            w4.x -= u4.x; w4.y -= u4.y; w4.z -= u4.z; w4.w -= u4.w;
        }
        f2h2_split(w4.x, w4.y, wh[i].x, wl[i].x);
        f2h2_split(w4.z, w4.w, wh[i].y, wl[i].y);
    }
}

__device__ __forceinline__ void store_stage(char* base, int t, int i,
                                            uint2 ah, uint2 al, uint2 wh, uint2 wl) {
    int cid = t + i * 256;
    int off = ((cid >> 3) * LDSH + (cid & 7) * 4) * 2;
    *(uint2*)(base + 0 * TILE_B + off) = ah;
    *(uint2*)(base + 1 * TILE_B + off) = al;
    *(uint2*)(base + 2 * TILE_B + off) = wh;
    *(uint2*)(base + 3 * TILE_B + off) = wl;
}

#define MMA_16816(ACC, AF, B0, B1)                                              \
    asm volatile(                                                               \
        "mma.sync.aligned.m16n8k16.row.col.f32.f16.f16.f32 "                    \
        "{%0,%1,%2,%3}, {%4,%5,%6,%7}, {%8,%9}, {%0,%1,%2,%3};"                 \
        : "+f"(ACC[0]), "+f"(ACC[1]), "+f"(ACC[2]), "+f"(ACC[3])                \
        : "r"(AF[0]), "r"(AF[1]), "r"(AF[2]), "r"(AF[3]), "r"(B0), "r"(B1))

template<int AMODE, bool WSUB, int EPI>
__global__ void __launch_bounds__(256) k_gemm_mma(
    const float* __restrict__ A,
    const float* __restrict__ Pg,
    const float* __restrict__ Pc,
    const float* __restrict__ scale,
    const float* __restrict__ shift,
    const float* __restrict__ W,
    const float* __restrict__ Wsub,
    int ldw,
    float* __restrict__ Cout,
    float* __restrict__ maxOut,
    float* __restrict__ minOut,
    int N, int K, int stage)
{
    extern __shared__ __align__(16) char sm[];
    __shared__ int grs[128];

    const int t = threadIdx.x;
    const int m0 = blockIdx.y * 128;
    const int n0 = blockIdx.x * 128;
    const int lane = t & 31;
    const int wid = t >> 5;
    const int mw = (wid >> 2) * 64;
    const int nw = (wid & 3) * 32;

    if (AMODE == 1) {
        if (t < 128) grs[t] = d_gidx[m0 + t];
        __syncthreads();
    }

    float acc[4][4][4];
#pragma unroll
    for (int a = 0; a < 4; a++)
#pragma unroll
        for (int b = 0; b < 4; b++)
#pragma unroll
            for (int cidx = 0; cidx < 4; cidx++) acc[a][b][cidx] = 0.0f;

    const uint32_t sBase = smem_u32(sm);

    uint2 ah[4], al[4], wh[4], wl[4];
    fetch_tiles<AMODE, WSUB>(ah, al, wh, wl, A, Pg, Pc, scale, shift, W, Wsub, ldw,
                             grs, m0, n0, K, 0, t);
#pragma unroll
    for (int i = 0; i < 4; i++) store_stage(sm, t, i, ah[i], al[i], wh[i], wl[i]);
    __syncthreads();

    const int lrow = ((lane >> 3) & 1) * 8 + (lane & 7);
    const int lcol = (lane >> 4) * 8;

    const int nch = K >> 5;
    for (int it = 0; it < nch; ++it) {
        const int s = it & 1;
        if (it + 1 < nch)
            fetch_tiles<AMODE, WSUB>(ah, al, wh, wl, A, Pg, Pc, scale, shift, W, Wsub, ldw,
                                     grs, m0, n0, K, (it + 1) << 5, t);
        const uint32_t stg = sBase + s * STAGE_B;
#pragma unroll
        for (int ks = 0; ks < 2; ks++) {
            const int k0 = ks * 16;
            uint32_t afh[4][4], afl[4][4];
#pragma unroll
            for (int mt = 0; mt < 4; mt++) {
                uint32_t addr = stg + ((mw + mt * 16 + lrow) * LDSH + k0 + lcol) * 2;
                asm volatile("ldmatrix.sync.aligned.m8n8.x4.shared.b16 {%0,%1,%2,%3}, [%4];"
                             : "=r"(afh[mt][0]), "=r"(afh[mt][1]), "=r"(afh[mt][2]), "=r"(afh[mt][3])
                             : "r"(addr));
                asm volatile("ldmatrix.sync.aligned.m8n8.x4.shared.b16 {%0,%1,%2,%3}, [%4];"
                             : "=r"(afl[mt][0]), "=r"(afl[mt][1]), "=r"(afl[mt][2]), "=r"(afl[mt][3])
                             : "r"(addr + TILE_B));
            }
            uint32_t bfh[4][2], bfl[4][2];
#pragma unroll
            for (int nt = 0; nt < 4; nt++) {
                const char* bp = sm + s * STAGE_B + 2 * TILE_B +
                    ((nw + nt * 8 + (lane >> 2)) * LDSH + k0 + 2 * (lane & 3)) * 2;
                bfh[nt][0] = *(const uint32_t*)bp;
                bfh[nt][1] = *(const uint32_t*)(bp + 16);
                bfl[nt][0] = *(const uint32_t*)(bp + TILE_B);
                bfl[nt][1] = *(const uint32_t*)(bp + TILE_B + 16);
            }
#pragma unroll
            for (int mt = 0; mt < 4; mt++)
#pragma unroll
                for (int nt = 0; nt < 4; nt++) {
                    MMA_16816(acc[mt][nt], afh[mt], bfh[nt][0], bfh[nt][1]);
                    MMA_16816(acc[mt][nt], afh[mt], bfl[nt][0], bfl[nt][1]);
                    MMA_16816(acc[mt][nt], afl[mt], bfh[nt][0], bfh[nt][1]);
                }
        }
        if (it + 1 < nch) {
            char* nb = sm + ((it + 1) & 1) * STAGE_B;
            __syncthreads();
#pragma unroll
            for (int i = 0; i < 4; i++) store_stage(nb, t, i, ah[i], al[i], wh[i], wl[i]);
            __syncthreads();
        }
    }

    // ---- epilogue ----
    if (EPI == 0 || EPI == 1) {
#pragma unroll
        for (int mt = 0; mt < 4; mt++) {
            int r0 = m0 + mw + mt * 16 + (lane >> 2);
#pragma unroll
            for (int nt = 0; nt < 4; nt++) {
                int c = n0 + nw + nt * 8 + 2 * (lane & 3);
                *(float2*)&Cout[(size_t)r0 * N + c] =
                    make_float2(acc[mt][nt][0], acc[mt][nt][1]);
                *(float2*)&Cout[(size_t)(r0 + 8) * N + c] =
                    make_float2(acc[mt][nt][2], acc[mt][nt][3]);
            }
        }
    }
    if (EPI >= 1) {
        // dump accumulators into smem scratch (stride 130 floats), re-read column-wise
        __syncthreads();
        float* scr = (float*)sm;
#pragma unroll
        for (int mt = 0; mt < 4; mt++) {
            int rl = mw + mt * 16 + (lane >> 2);
#pragma unroll
            for (int nt = 0; nt < 4; nt++) {
                int c = nw + nt * 8 + 2 * (lane & 3);
                *(float2*)&scr[rl * 130 + c] = make_float2(acc[mt][nt][0], acc[mt][nt][1]);
                *(float2*)&scr[(rl + 8) * 130 + c] = make_float2(acc[mt][nt][2], acc[mt][nt][3]);
            }
        }
        __syncthreads();
        const int c = t & 127;
        const int half = t >> 7;
        float s = 0.0f, q = 0.0f;
        if (EPI == 2) {
#pragma unroll
            for (int p = 0; p < 8; p++) {
                float mx = -3.4e38f, mn = 3.4e38f;
#pragma unroll
                for (int i = 0; i < 8; i++) {
                    float v = scr[((half * 8 + p) * 8 + i) * 130 + c];
                    mx = fmaxf(mx, v); mn = fminf(mn, v);
                    s += v; q = fmaf(v, v, q);
                }
                size_t gp = (size_t)((m0 >> 3) + half * 8 + p) * N + n0 + c;
                maxOut[gp] = mx;
                minOut[gp] = mn;
            }
        } else {
            for (int r = 0; r < 64; r++) {
                float v = scr[(half * 64 + r) * 130 + c];
                s += v; q = fmaf(v, v, q);
            }
        }
        atomicAdd(&d_sum[stage][n0 + c], s);
        atomicAdd(&d_ssq[stage][n0 + c], q);
    }
}

// ---------------- h = bn_relu(t2) elementwise (8192x256) ----------------
__global__ void k_h() {
    int t = blockIdx.x * 256 + threadIdx.x;
    float4 v = ((const float4*)d_t2)[t];
    int c0 = (t * 4) & 255;
    v.x = fmaxf(fmaf(v.x, d_scale[1][c0 + 0], d_shift[1][c0 + 0]), 0.0f);
    v.y = fmaxf(fmaf(v.y, d_scale[1][c0 + 1], d_shift[1][c0 + 1]), 0.0f);
    v.z = fmaxf(fmaf(v.z, d_scale[1][c0 + 2], d_shift[1][c0 + 2]), 0.0f);
    v.w = fmaxf(fmaf(v.w, d_scale[1][c0 + 3], d_shift[1][c0 + 3]), 0.0f);
    ((float4*)d_h)[t] = v;
}

// ---------------- kNN (k=8) on xyz ----------------
__global__ void k_knn(const float* __restrict__ xyz) {
    __shared__ float sx[1024], sy[1024], sz[1024], sq[1024];
    int b = blockIdx.x >> 2;
    int q0 = (blockIdx.x & 3) * 256;
    int t = threadIdx.x;
    for (int i = t; i < 1024; i += 256) {
        float x = xyz[(b * 1024 + i) * 3 + 0];
        float y = xyz[(b * 1024 + i) * 3 + 1];
        float z = xyz[(b * 1024 + i) * 3 + 2];
        sx[i] = x; sy[i] = y; sz[i] = z;
        sq[i] = fmaf(z, z, fmaf(y, y, x * x));
    }
    __syncthreads();
    int qi = q0 + t;
    float qx = sx[qi], qy = sy[qi], qz = sz[qi], qs = sq[qi];
    float bd[8]; int bi[8];
#pragma unroll
    for (int k = 0; k < 8; k++) { bd[k] = 3.4e38f; bi[k] = 0; }
    for (int m = 0; m < 1024; m++) {
        float dot = fmaf(qz, sz[m], fmaf(qy, sy[m], qx * sx[m]));
        float d = (qs + sq[m]) - 2.0f * dot;
        if (d < bd[7]) {
#pragma unroll
            for (int j = 7; j > 0; j--) {
                bool gt  = bd[j] > d;
                bool gtp = bd[j - 1] > d;
                if (gt) {
                    bd[j] = gtp ? bd[j - 1] : d;
                    bi[j] = gtp ? bi[j - 1] : m;
                }
            }
            if (bd[0] > d) { bd[0] = d; bi[0] = m; }
        }
    }
#pragma unroll
    for (int k = 0; k < 8; k++)
        d_gidx[(b * 1024 + qi) * 8 + k] = b * 1024 + bi[k];
}

// ---------------- stats of u = Pg[gidx[r]] + Pc[r>>3] over 65536 rows ----------------
__global__ void k_stats_u(const float* __restrict__ Pg, const float* __restrict__ Pc,
                          int Cn, int stage) {
    int t = threadIdx.x;
    int r0 = blockIdx.x * 64;
    float accS[4] = {0, 0, 0, 0}, accQ[4] = {0, 0, 0, 0};
    for (int i = 0; i < 64; i++) {
        int r = r0 + i;
        const float* pg = Pg + (size_t)d_gidx[r] * Cn;
        const float* pc = Pc + (size_t)(r >> 3) * Cn;
#pragma unroll
        for (int j = 0; j < 4; j++) {
            int c = t + j * 256;
            if (c < Cn) {
                float v = pg[c] + pc[c];
                accS[j] += v;
                accQ[j] = fmaf(v, v, accQ[j]);
            }
        }
    }
#pragma unroll
    for (int j = 0; j < 4; j++) {
        int c = t + j * 256;
        if (c < Cn) {
            atomicAdd(&d_sum[stage][c], accS[j]);
            atomicAdd(&d_ssq[stage][c], accQ[j]);
        }
    }
}

// ---------------- l0 = bn_relu applied to max/min-selected raw pool (8192x512) ----------------
__global__ void k_l0_final() {
    int t = blockIdx.x * 256 + threadIdx.x;   // over 8192*128 float4
    int c = (t & 127) * 4;
    float4 s4 = *(const float4*)&d_scale[3][c];
    float4 h4 = *(const float4*)&d_shift[3][c];
    float4 mx = *(const float4*)&d_maxA[(size_t)t * 4];
    float4 mn = *(const float4*)&d_minA[(size_t)t * 4];
    float4 r;
    r.x = fmaxf(fmaf(s4.x >= 0.0f ? mx.x : mn.x, s4.x, h4.x), 0.0f);
    r.y = fmaxf(fmaf(s4.y >= 0.0f ? mx.y : mn.y, s4.y, h4.y), 0.0f);
    r.z = fmaxf(fmaf(s4.z >= 0.0f ? mx.z : mn.z, s4.z, h4.z), 0.0f);
    r.w = fmaxf(fmaf(s4.w >= 0.0f ? mx.w : mn.w, s4.w, h4.w), 0.0f);
    *(float4*)&d_l0[(size_t)t * 4] = r;
}

// ---------------- out[b,o,n] = bn_relu(select(maxB/minB)) transposed ----------------
__global__ void k_out_final(float* __restrict__ out) {
    __shared__ float tile[32][33];
    int b = blockIdx.z;
    int o0 = blockIdx.x * 32;
    int n0 = blockIdx.y * 32;
    int tx = threadIdx.x, ty = threadIdx.y;
    float sc = d_scale[5][o0 + tx];
    float sh = d_shift[5][o0 + tx];
#pragma unroll
    for (int jj = 0; jj < 4; jj++) {
        int nl = ty + jj * 8;
        size_t idx = (size_t)(b * 1024 + n0 + nl) * 1024 + o0 + tx;
        float v = sc >= 0.0f ? d_maxB[idx] : d_minB[idx];
        tile[tx][nl] = fmaxf(fmaf(v, sc, sh), 0.0f);
    }
    __syncthreads();
#pragma unroll
    for (int jj = 0; jj < 4; jj++) {
        int ol = ty + jj * 8;
        out[((size_t)(b * 1024) + o0 + ol) * 1024 + n0 + tx] = tile[ol][tx];
    }
}

// ================= host launcher =================
extern "C" void kernel_launch(void* const* d_in, const int* in_sizes, int n_in,
                              void* d_out, int out_size) {
    const float* xyz = (const float*)d_in[0];
    const float* W1  = (const float*)d_in[1];
    const float* g1  = (const float*)d_in[2];
    const float* b1  = (const float*)d_in[3];
    const float* W2  = (const float*)d_in[4];
    const float* g2  = (const float*)d_in[5];
    const float* b2  = (const float*)d_in[6];
    const float* WA1 = (const float*)d_in[7];
    const float* gA1 = (const float*)d_in[8];
    const float* bA1 = (const float*)d_in[9];
    const float* WA2 = (const float*)d_in[10];
    const float* gA2 = (const float*)d_in[11];
    const float* bA2 = (const float*)d_in[12];
    const float* WB1 = (const float*)d_in[13];
    const float* gB1 = (const float*)d_in[14];
    const float* bB1 = (const float*)d_in[15];
    const float* WB2 = (const float*)d_in[16];
    const float* gB2 = (const float*)d_in[17];
    const float* bB2 = (const float*)d_in[18];

    float *pt1, *pt2, *ph, *pPgA, *pPcA, *pl0, *pPgB, *pPcB;
    float *pMaxA, *pMinA, *pMaxB, *pMinB;
    float *pScale, *pShift;
    cudaGetSymbolAddress((void**)&pt1,  d_t1);
    cudaGetSymbolAddress((void**)&pt2,  d_t2);
    cudaGetSymbolAddress((void**)&ph,   d_h);
    cudaGetSymbolAddress((void**)&pPgA, d_PgA);
    cudaGetSymbolAddress((void**)&pPcA, d_PcA);
    cudaGetSymbolAddress((void**)&pl0,  d_l0);
    cudaGetSymbolAddress((void**)&pPgB, d_PgB);
    cudaGetSymbolAddress((void**)&pPcB, d_PcB);
    cudaGetSymbolAddress((void**)&pMaxA, d_maxA);
    cudaGetSymbolAddress((void**)&pMinA, d_minA);
    cudaGetSymbolAddress((void**)&pMaxB, d_maxB);
    cudaGetSymbolAddress((void**)&pMinB, d_minB);
    cudaGetSymbolAddress((void**)&pScale, d_scale);
    cudaGetSymbolAddress((void**)&pShift, d_shift);

    cudaFuncSetAttribute(k_gemm_mma<0, false, 0>, cudaFuncAttributeMaxDynamicSharedMemorySize, GSMEM);
    cudaFuncSetAttribute(k_gemm_mma<0, true , 0>, cudaFuncAttributeMaxDynamicSharedMemorySize, GSMEM);
    cudaFuncSetAttribute(k_gemm_mma<1, false, 2>, cudaFuncAttributeMaxDynamicSharedMemorySize, GSMEM);
    cudaFuncSetAttribute(k_gemm_mma<2, false, 1>, cudaFuncAttributeMaxDynamicSharedMemorySize, GSMEM);

    k_init_stats<<<24, 256>>>();

    // MLP stage 1: t1 + stats0
    k_t1<<<256, 256>>>(xyz, W1);
    k_finalize<<<1, 64>>>(0, 64, 8192.0f, g1, b1);

    // MLP stage 2: t2 = bn_relu(t1) @ W2^T  (+fused stats stage1)
    k_gemm_mma<2, false, 1><<<dim3(2, 64), 256, GSMEM>>>(
        pt1, nullptr, nullptr, pScale + 0 * 1024, pShift + 0 * 1024,
        W2, nullptr, 64, pt2, nullptr, nullptr, 256, 64, 1);
    k_finalize<<<1, 256>>>(1, 256, 8192.0f, g2, b2);
    k_h<<<2048, 256>>>();

    // kNN
    k_knn<<<32, 256>>>(xyz);

    // local_op A, layer 1 factored: PgA = h @ WA1g^T ; PcA = h @ (WA1c-WA1g)^T
    k_gemm_mma<0, false, 0><<<dim3(4, 64), 256, GSMEM>>>(
        ph, nullptr, nullptr, nullptr, nullptr, WA1, nullptr, 512,
        pPgA, nullptr, nullptr, 512, 256, 0);
    k_gemm_mma<0, true, 0><<<dim3(4, 64), 256, GSMEM>>>(
        ph, nullptr, nullptr, nullptr, nullptr, WA1 + 256, WA1, 512,
        pPcA, nullptr, nullptr, 512, 256, 0);
    k_stats_u<<<1024, 256>>>(pPgA, pPcA, 512, 2);
    k_finalize<<<2, 256>>>(2, 512, 65536.0f, gA1, bA1);

    // local_op A, layer 2: fused stats(3) + per-point max/min (UA never materialized)
    k_gemm_mma<1, false, 2><<<dim3(4, 512), 256, GSMEM>>>(
        nullptr, pPgA, pPcA, pScale + 2 * 1024, pShift + 2 * 1024,
        WA2, nullptr, 512, nullptr, pMaxA, pMinA, 512, 512, 3);
    k_finalize<<<2, 256>>>(3, 512, 65536.0f, gA2, bA2);
    k_l0_final<<<4096, 256>>>();

    // local_op B, layer 1 factored
    k_gemm_mma<0, false, 0><<<dim3(8, 64), 256, GSMEM>>>(
        pl0, nullptr, nullptr, nullptr, nullptr, WB1, nullptr, 1024,
        pPgB, nullptr, nullptr, 1024, 512, 0);
    k_gemm_mma<0, true, 0><<<dim3(8, 64), 256, GSMEM>>>(
        pl0, nullptr, nullptr, nullptr, nullptr, WB1 + 512, WB1, 1024,
        pPcB, nullptr, nullptr, 1024, 512, 0);
    k_stats_u<<<1024, 256>>>(pPgB, pPcB, 1024, 4);
    k_finalize<<<4, 256>>>(4, 1024, 65536.0f, gB1, bB1);

    // local_op B, layer 2 (dominant GEMM): fused stats(5) + max/min (UB never materialized)
    k_gemm_mma<1, false, 2><<<dim3(8, 512), 256, GSMEM>>>(
        nullptr, pPgB, pPcB, pScale + 4 * 1024, pShift + 4 * 1024,
        WB2, nullptr, 1024, nullptr, pMaxB, pMinB, 1024, 1024, 5);
    k_finalize<<<4, 256>>>(5, 1024, 65536.0f, gB2, bB2);

    // final: bn_relu(select(max/min)) + transpose to (B, C, N)
    k_out_final<<<dim3(32, 32, 8), dim3(32, 8)>>>((float*)d_out);
}

// round 7
// speedup vs baseline: 1.9604x; 1.0660x over previous
#include <cuda_runtime.h>
#include <cuda_fp16.h>
#include <math.h>
#include <stdint.h>

#define EPSBN 1e-5f

// ---------------- scratch (static device globals; no allocation) ----------------
__device__ float d_t1 [8192 * 64];
__device__ float d_t2 [8192 * 256];
__device__ int   d_gidx[8192 * 8];
__device__ float d_PgA[8192 * 512];
__device__ float d_PcA[8192 * 512];
__device__ float d_maxA[8192 * 512];
__device__ float d_minA[8192 * 512];
__device__ uint32_t d_l0p[8192 * 512];        // packed split-fp16 l0
__device__ float d_PgB[8192 * 1024];
__device__ float d_PcB[8192 * 1024];
__device__ float d_maxB[8192 * 1024];
__device__ float d_minB[8192 * 1024];

// packed split weights
__device__ uint32_t d_W2p [256 * 64];
__device__ uint32_t d_WA1g[512 * 256];
__device__ uint32_t d_WA1d[512 * 256];
__device__ uint32_t d_WA2p[512 * 512];
__device__ uint32_t d_WB1g[1024 * 512];
__device__ uint32_t d_WB1d[1024 * 512];
__device__ uint32_t d_WB2p[1024 * 1024];

__device__ float d_sum  [6][1024];
__device__ float d_ssq  [6][1024];
__device__ float d_scale[6][1024];
__device__ float d_shift[6][1024];

__device__ __forceinline__ uint32_t smem_u32(const void* p) {
    uint32_t a;
    asm("{ .reg .u64 t; cvta.to.shared.u64 t, %1; cvt.u32.u64 %0, t; }" : "=r"(a) : "l"(p));
    return a;
}
__device__ __forceinline__ uint32_t prmt(uint32_t a, uint32_t b, uint32_t sel) {
    uint32_t r;
    asm("prmt.b32 %0, %1, %2, %3;" : "=r"(r) : "r"(a), "r"(b), "r"(sel));
    return r;
}
__device__ __forceinline__ uint32_t packhl(float x) {
    __half h = __float2half_rn(x);
    __half l = __float2half_rn(x - __half2float(h));
    return (uint32_t)__half_as_ushort(h) | ((uint32_t)__half_as_ushort(l) << 16);
}
// split (a,b) into hi fp16 pair and lo (residual) fp16 pair
__device__ __forceinline__ void f2h2_split(float a, float b, uint32_t& hi, uint32_t& lo) {
    __half2 h = __floats2half2_rn(a, b);
    float2 hf = __half22float2(h);
    __half2 l = __floats2half2_rn(a - hf.x, b - hf.y);
    hi = *reinterpret_cast<uint32_t*>(&h);
    lo = *reinterpret_cast<uint32_t*>(&l);
}

// ---------------- init: zero stat accumulators ----------------
__global__ void k_init_stats() {
    int t = blockIdx.x * blockDim.x + threadIdx.x;
    if (t < 6 * 1024) {
        (&d_sum[0][0])[t] = 0.0f;
        (&d_ssq[0][0])[t] = 0.0f;
    }
}

// ---------------- pack weights: out[i] = packhl(Wa[r*ldw+c] - Wsub[r*ldw+c]) ----------------
__global__ void k_pack(const float* __restrict__ Wa, const float* __restrict__ Wsub,
                       uint32_t* __restrict__ out, int cols, int ldw, int total) {
    int i = blockIdx.x * 256 + threadIdx.x;
    if (i < total) {
        int r = i / cols, c = i - r * cols;
        float v = Wa[(size_t)r * ldw + c];
        if (Wsub) v -= Wsub[(size_t)r * ldw + c];
        out[i] = packhl(v);
    }
}

// ---------------- t1 = xyz @ W1^T  (8192x64, K=3) + stats stage0 ----------------
__global__ void k_t1(const float* __restrict__ xyz, const float* __restrict__ W1) {
    __shared__ float w[64][3];
    __shared__ float shs[4][64], shq[4][64];
    int t = threadIdx.x;
    int ch = t & 63, rg = t >> 6;
    if (t < 192) (&w[0][0])[t] = W1[t];
    __syncthreads();
    int r0 = blockIdx.x * 32 + rg * 8;
    float w0 = w[ch][0], w1 = w[ch][1], w2 = w[ch][2];
    float s = 0.0f, q = 0.0f;
#pragma unroll
    for (int i = 0; i < 8; i++) {
        int r = r0 + i;
        float x = xyz[r * 3 + 0], y = xyz[r * 3 + 1], z = xyz[r * 3 + 2];
        float v = fmaf(z, w2, fmaf(y, w1, x * w0));
        d_t1[r * 64 + ch] = v;
        s += v; q = fmaf(v, v, q);
    }
    shs[rg][ch] = s; shq[rg][ch] = q;
    __syncthreads();
    if (rg == 0) {
        s = shs[0][ch] + shs[1][ch] + shs[2][ch] + shs[3][ch];
        q = shq[0][ch] + shq[1][ch] + shq[2][ch] + shq[3][ch];
        atomicAdd(&d_sum[0][ch], s);
        atomicAdd(&d_ssq[0][ch], q);
    }
}

// ---------------- finalize BN stats -> scale/shift ----------------
__global__ void k_finalize(int stage, int C, float count,
                           const float* __restrict__ g, const float* __restrict__ b) {
    int c = blockIdx.x * blockDim.x + threadIdx.x;
    if (c < C) {
        float m = d_sum[stage][c] / count;
        float v = d_ssq[stage][c] / count - m * m;
        float s = g[c] / sqrtf(v + EPSBN);
        d_scale[stage][c] = s;
        d_shift[stage][c] = fmaf(-m, s, b[c]);
    }
}

// ================= split-precision fp16 mma GEMM: C[M,N] = Arows @ W^T =================
// BM=128, BN=128, BK=32. 512 threads = 16 warps (4 x 4), warp tile 32x32.
// x = xh + xl (fp16 pair). C = Ah*Bh + Ah*Bl + Al*Bh, fp32 accum.
// W always packed split (h | l<<16), precomputed.
// AMODE 0: A packed split. AMODE 2: bn_relu(raw A). AMODE 1: bn_relu(Pg[gidx]+Pc).
// EPI 0: plain store. EPI 1: store + column stats. EPI 2: per-point max/min + stats.

static constexpr int LDSH = 40;                        // halves per smem row (80B)
static constexpr int TILE_B = 128 * LDSH * 2;          // 10240 bytes per tile
static constexpr int STAGE_B = 4 * TILE_B;             // Ah,Al,Bh,Bl
static constexpr int GSMEM = 2 * STAGE_B;              // 81920 bytes (>= 128*130*4 scratch)

template<int AMODE>
__device__ __forceinline__ void fetch_tiles(
    uint2 ah[2], uint2 al[2], uint2 wh[2], uint2 wl[2],
    const float* __restrict__ A, const uint32_t* __restrict__ Ap,
    const float* __restrict__ Pg, const float* __restrict__ Pc,
    const float* __restrict__ scale, const float* __restrict__ shift,
    const uint32_t* __restrict__ Wp,
    const int* grs, int m0, int n0, int K, int k0, int t)
{
#pragma unroll
    for (int i = 0; i < 2; i++) {
        int cid = t + i * 512;
        int r = cid >> 3;
        int c = k0 + (cid & 7) * 4;
        if (AMODE == 0) {
            uint4 P = *(const uint4*)(Ap + (size_t)(m0 + r) * K + c);
            ah[i].x = prmt(P.x, P.y, 0x5410); al[i].x = prmt(P.x, P.y, 0x7632);
            ah[i].y = prmt(P.z, P.w, 0x5410); al[i].y = prmt(P.z, P.w, 0x7632);
        } else if (AMODE == 2) {
            float4 x = *(const float4*)(A + (size_t)(m0 + r) * K + c);
            float4 s4 = *(const float4*)(scale + c);
            float4 h4 = *(const float4*)(shift + c);
            float4 v;
            v.x = fmaxf(fmaf(x.x, s4.x, h4.x), 0.0f);
            v.y = fmaxf(fmaf(x.y, s4.y, h4.y), 0.0f);
            v.z = fmaxf(fmaf(x.z, s4.z, h4.z), 0.0f);
            v.w = fmaxf(fmaf(x.w, s4.w, h4.w), 0.0f);
            f2h2_split(v.x, v.y, ah[i].x, al[i].x);
            f2h2_split(v.z, v.w, ah[i].y, al[i].y);
        } else {
            float4 g4 = *(const float4*)(Pg + (size_t)grs[r] * K + c);
            float4 c4 = *(const float4*)(Pc + (size_t)((m0 + r) >> 3) * K + c);
            float4 s4 = *(const float4*)(scale + c);
            float4 h4 = *(const float4*)(shift + c);
            float4 v;
            v.x = fmaxf(fmaf(g4.x + c4.x, s4.x, h4.x), 0.0f);
            v.y = fmaxf(fmaf(g4.y + c4.y, s4.y, h4.y), 0.0f);
            v.z = fmaxf(fmaf(g4.z + c4.z, s4.z, h4.z), 0.0f);
            v.w = fmaxf(fmaf(g4.w + c4.w, s4.w, h4.w), 0.0f);
            f2h2_split(v.x, v.y, ah[i].x, al[i].x);
            f2h2_split(v.z, v.w, ah[i].y, al[i].y);
        }
        uint4 Q = *(const uint4*)(Wp + (size_t)(n0 + r) * K + c);
        wh[i].x = prmt(Q.x, Q.y, 0x5410); wl[i].x = prmt(Q.x, Q.y, 0x7632);
        wh[i].y = prmt(Q.z, Q.w, 0x5410); wl[i].y = prmt(Q.z, Q.w, 0x7632);
    }
}

__device__ __forceinline__ void store_stage(char* base, int t, int i,
                                            uint2 ah, uint2 al, uint2 wh, uint2 wl) {
    int cid = t + i * 512;
    int off = ((cid >> 3) * LDSH + (cid & 7) * 4) * 2;
    *(uint2*)(base + 0 * TILE_B + off) = ah;
    *(uint2*)(base + 1 * TILE_B + off) = al;
    *(uint2*)(base + 2 * TILE_B + off) = wh;
    *(uint2*)(base + 3 * TILE_B + off) = wl;
}

#define MMA_16816(ACC, AF, B0, B1)                                              \
    asm volatile(                                                               \
        "mma.sync.aligned.m16n8k16.row.col.f32.f16.f16.f32 "                    \
        "{%0,%1,%2,%3}, {%4,%5,%6,%7}, {%8,%9}, {%0,%1,%2,%3};"                 \
        : "+f"(ACC[0]), "+f"(ACC[1]), "+f"(ACC[2]), "+f"(ACC[3])                \
        : "r"(AF[0]), "r"(AF[1]), "r"(AF[2]), "r"(AF[3]), "r"(B0), "r"(B1))

template<int AMODE, int EPI>
__global__ void __launch_bounds__(512) k_gemm_mma(
    const float* __restrict__ A,
    const uint32_t* __restrict__ Ap,
    const float* __restrict__ Pg,
    const float* __restrict__ Pc,
    const float* __restrict__ scale,
    const float* __restrict__ shift,
    const uint32_t* __restrict__ Wp,
    float* __restrict__ Cout,
    float* __restrict__ maxOut,
    float* __restrict__ minOut,
    int N, int K, int stage)
{
    extern __shared__ __align__(16) char sm[];
    __shared__ int grs[128];

    const int t = threadIdx.x;
    const int m0 = blockIdx.y * 128;
    const int n0 = blockIdx.x * 128;
    const int lane = t & 31;
    const int wid = t >> 5;
    const int mw = (wid >> 2) * 32;
    const int nw = (wid & 3) * 32;

    if (AMODE == 1) {
        if (t < 128) grs[t] = d_gidx[m0 + t];
        __syncthreads();
    }

    float acc[2][4][4];
#pragma unroll
    for (int a = 0; a < 2; a++)
#pragma unroll
        for (int b = 0; b < 4; b++)
#pragma unroll
            for (int cidx = 0; cidx < 4; cidx++) acc[a][b][cidx] = 0.0f;

    const uint32_t sBase = smem_u32(sm);

    uint2 ah[2], al[2], wh[2], wl[2];
    fetch_tiles<AMODE>(ah, al, wh, wl, A, Ap, Pg, Pc, scale, shift, Wp,
                       grs, m0, n0, K, 0, t);
#pragma unroll
    for (int i = 0; i < 2; i++) store_stage(sm, t, i, ah[i], al[i], wh[i], wl[i]);
    __syncthreads();

    const int lrow = ((lane >> 3) & 1) * 8 + (lane & 7);
    const int lcol = (lane >> 4) * 8;

    const int nch = K >> 5;
    for (int it = 0; it < nch; ++it) {
        const int s = it & 1;
        if (it + 1 < nch)
            fetch_tiles<AMODE>(ah, al, wh, wl, A, Ap, Pg, Pc, scale, shift, Wp,
                               grs, m0, n0, K, (it + 1) << 5, t);
        const uint32_t stg = sBase + s * STAGE_B;
#pragma unroll
        for (int ks = 0; ks < 2; ks++) {
            const int k0 = ks * 16;
            uint32_t afh[2][4], afl[2][4];
#pragma unroll
            for (int mt = 0; mt < 2; mt++) {
                uint32_t addr = stg + ((mw + mt * 16 + lrow) * LDSH + k0 + lcol) * 2;
                asm volatile("ldmatrix.sync.aligned.m8n8.x4.shared.b16 {%0,%1,%2,%3}, [%4];"
                             : "=r"(afh[mt][0]), "=r"(afh[mt][1]), "=r"(afh[mt][2]), "=r"(afh[mt][3])
                             : "r"(addr));
                asm volatile("ldmatrix.sync.aligned.m8n8.x4.shared.b16 {%0,%1,%2,%3}, [%4];"
                             : "=r"(afl[mt][0]), "=r"(afl[mt][1]), "=r"(afl[mt][2]), "=r"(afl[mt][3])
                             : "r"(addr + TILE_B));
            }
            uint32_t bfh[4][2], bfl[4][2];
#pragma unroll
            for (int nt = 0; nt < 4; nt++) {
                const char* bp = sm + s * STAGE_B + 2 * TILE_B +
                    ((nw + nt * 8 + (lane >> 2)) * LDSH + k0 + 2 * (lane & 3)) * 2;
                bfh[nt][0] = *(const uint32_t*)bp;
                bfh[nt][1] = *(const uint32_t*)(bp + 16);
                bfl[nt][0] = *(const uint32_t*)(bp + TILE_B);
                bfl[nt][1] = *(const uint32_t*)(bp + TILE_B + 16);
            }
#pragma unroll
            for (int mt = 0; mt < 2; mt++)
#pragma unroll
                for (int nt = 0; nt < 4; nt++) {
                    MMA_16816(acc[mt][nt], afh[mt], bfh[nt][0], bfh[nt][1]);
                    MMA_16816(acc[mt][nt], afh[mt], bfl[nt][0], bfl[nt][1]);
                    MMA_16816(acc[mt][nt], afl[mt], bfh[nt][0], bfh[nt][1]);
                }
        }
        if (it + 1 < nch) {
            char* nb = sm + ((it + 1) & 1) * STAGE_B;
            __syncthreads();
#pragma unroll
            for (int i = 0; i < 2; i++) store_stage(nb, t, i, ah[i], al[i], wh[i], wl[i]);
            __syncthreads();
        }
    }

    // ---- epilogue ----
    if (EPI == 0 || EPI == 1) {
#pragma unroll
        for (int mt = 0; mt < 2; mt++) {
            int r0 = m0 + mw + mt * 16 + (lane >> 2);
#pragma unroll
            for (int nt = 0; nt < 4; nt++) {
                int c = n0 + nw + nt * 8 + 2 * (lane & 3);
                *(float2*)&Cout[(size_t)r0 * N + c] =
                    make_float2(acc[mt][nt][0], acc[mt][nt][1]);
                *(float2*)&Cout[(size_t)(r0 + 8) * N + c] =
                    make_float2(acc[mt][nt][2], acc[mt][nt][3]);
            }
        }
    }
    if (EPI >= 1) {
        // dump accumulators into smem scratch (stride 130 floats), re-read column-wise
        __syncthreads();
        float* scr = (float*)sm;
#pragma unroll
        for (int mt = 0; mt < 2; mt++) {
            int rl = mw + mt * 16 + (lane >> 2);
#pragma unroll
            for (int nt = 0; nt < 4; nt++) {
                int c = nw + nt * 8 + 2 * (lane & 3);
                *(float2*)&scr[rl * 130 + c] = make_float2(acc[mt][nt][0], acc[mt][nt][1]);
                *(float2*)&scr[(rl + 8) * 130 + c] = make_float2(acc[mt][nt][2], acc[mt][nt][3]);
            }
        }
        __syncthreads();
        const int c = t & 127;
        const int quad = t >> 7;          // 0..3, 32 rows each
        float s = 0.0f, q = 0.0f;
        if (EPI == 2) {
#pragma unroll
            for (int p = 0; p < 4; p++) {
                float mx = -3.4e38f, mn = 3.4e38f;
#pragma unroll
                for (int i = 0; i < 8; i++) {
                    float v = scr[(quad * 32 + p * 8 + i) * 130 + c];
                    mx = fmaxf(mx, v); mn = fminf(mn, v);
                    s += v; q = fmaf(v, v, q);
                }
                size_t gp = (size_t)((m0 >> 3) + quad * 4 + p) * N + n0 + c;
                maxOut[gp] = mx;
                minOut[gp] = mn;
            }
        } else {
            for (int r = 0; r < 32; r++) {
                float v = scr[(quad * 32 + r) * 130 + c];
                s += v; q = fmaf(v, v, q);
            }
        }
        atomicAdd(&d_sum[stage][n0 + c], s);
        atomicAdd(&d_ssq[stage][n0 + c], q);
    }
}

// ---------------- kNN (k=8) on xyz ----------------
__global__ void k_knn(const float* __restrict__ xyz) {
    __shared__ float sx[1024], sy[1024], sz[1024], sq[1024];
    int b = blockIdx.x >> 2;
    int q0 = (blockIdx.x & 3) * 256;
    int t = threadIdx.x;
    for (int i = t; i < 1024; i += 256) {
        float x = xyz[(b * 1024 + i) * 3 + 0];
        float y = xyz[(b * 1024 + i) * 3 + 1];
        float z = xyz[(b * 1024 + i) * 3 + 2];
        sx[i] = x; sy[i] = y; sz[i] = z;
        sq[i] = fmaf(z, z, fmaf(y, y, x * x));
    }
    __syncthreads();
    int qi = q0 + t;
    float qx = sx[qi], qy = sy[qi], qz = sz[qi], qs = sq[qi];
    float bd[8]; int bi[8];
#pragma unroll
    for (int k = 0; k < 8; k++) { bd[k] = 3.4e38f; bi[k] = 0; }
    for (int m = 0; m < 1024; m++) {
        float dot = fmaf(qz, sz[m], fmaf(qy, sy[m], qx * sx[m]));
        float d = (qs + sq[m]) - 2.0f * dot;
        if (d < bd[7]) {
#pragma unroll
            for (int j = 7; j > 0; j--) {
                bool gt  = bd[j] > d;
                bool gtp = bd[j - 1] > d;
                if (gt) {
                    bd[j] = gtp ? bd[j - 1] : d;
                    bi[j] = gtp ? bi[j - 1] : m;
                }
            }
            if (bd[0] > d) { bd[0] = d; bi[0] = m; }
        }
    }
#pragma unroll
    for (int k = 0; k < 8; k++)
        d_gidx[(b * 1024 + qi) * 8 + k] = b * 1024 + bi[k];
}

// ---------------- stats of u = Pg[gidx[r]] + Pc[r>>3] over 65536 rows ----------------
__global__ void k_stats_u(const float* __restrict__ Pg, const float* __restrict__ Pc,
                          int Cn, int stage) {
    int t = threadIdx.x;
    int r0 = blockIdx.x * 64;
    float accS[4] = {0, 0, 0, 0}, accQ[4] = {0, 0, 0, 0};
    for (int i = 0; i < 64; i++) {
        int r = r0 + i;
        const float* pg = Pg + (size_t)d_gidx[r] * Cn;
        const float* pc = Pc + (size_t)(r >> 3) * Cn;
#pragma unroll
        for (int j = 0; j < 4; j++) {
            int c = t + j * 256;
            if (c < Cn) {
                float v = pg[c] + pc[c];
                accS[j] += v;
                accQ[j] = fmaf(v, v, accQ[j]);
            }
        }
    }
#pragma unroll
    for (int j = 0; j < 4; j++) {
        int c = t + j * 256;
        if (c < Cn) {
            atomicAdd(&d_sum[stage][c], accS[j]);
            atomicAdd(&d_ssq[stage][c], accQ[j]);
        }
    }
}

// ---------------- l0(packed) = pack(bn_relu(select(maxA/minA)))  (8192x512) ----------------
__global__ void k_l0_final() {
    int t = blockIdx.x * 256 + threadIdx.x;   // over 8192*128 float4
    int c = (t & 127) * 4;
    float4 s4 = *(const float4*)&d_scale[3][c];
    float4 h4 = *(const float4*)&d_shift[3][c];
    float4 mx = *(const float4*)&d_maxA[(size_t)t * 4];
    float4 mn = *(const float4*)&d_minA[(size_t)t * 4];
    uint4 o;
    o.x = packhl(fmaxf(fmaf(s4.x >= 0.0f ? mx.x : mn.x, s4.x, h4.x), 0.0f));
    o.y = packhl(fmaxf(fmaf(s4.y >= 0.0f ? mx.y : mn.y, s4.y, h4.y), 0.0f));
    o.z = packhl(fmaxf(fmaf(s4.z >= 0.0f ? mx.z : mn.z, s4.z, h4.z), 0.0f));
    o.w = packhl(fmaxf(fmaf(s4.w >= 0.0f ? mx.w : mn.w, s4.w, h4.w), 0.0f));
    *(uint4*)&d_l0p[(size_t)t * 4] = o;
}

// ---------------- out[b,o,n] = bn_relu(select(maxB/minB)) transposed ----------------
__global__ void k_out_final(float* __restrict__ out) {
    __shared__ float tile[32][33];
    int b = blockIdx.z;
    int o0 = blockIdx.x * 32;
    int n0 = blockIdx.y * 32;
    int tx = threadIdx.x, ty = threadIdx.y;
    float sc = d_scale[5][o0 + tx];
    float sh = d_shift[5][o0 + tx];
#pragma unroll
    for (int jj = 0; jj < 4; jj++) {
        int nl = ty + jj * 8;
        size_t idx = (size_t)(b * 1024 + n0 + nl) * 1024 + o0 + tx;
        float v = sc >= 0.0f ? d_maxB[idx] : d_minB[idx];
        tile[tx][nl] = fmaxf(fmaf(v, sc, sh), 0.0f);
    }
    __syncthreads();
#pragma unroll
    for (int jj = 0; jj < 4; jj++) {
        int ol = ty + jj * 8;
        out[((size_t)(b * 1024) + o0 + ol) * 1024 + n0 + tx] = tile[ol][tx];
    }
}

// ================= host launcher =================
extern "C" void kernel_launch(void* const* d_in, const int* in_sizes, int n_in,
                              void* d_out, int out_size) {
    const float* xyz = (const float*)d_in[0];
    const float* W1  = (const float*)d_in[1];
    const float* g1  = (const float*)d_in[2];
    const float* b1  = (const float*)d_in[3];
    const float* W2  = (const float*)d_in[4];
    const float* g2  = (const float*)d_in[5];
    const float* b2  = (const float*)d_in[6];
    const float* WA1 = (const float*)d_in[7];
    const float* gA1 = (const float*)d_in[8];
    const float* bA1 = (const float*)d_in[9];
    const float* WA2 = (const float*)d_in[10];
    const float* gA2 = (const float*)d_in[11];
    const float* bA2 = (const float*)d_in[12];
    const float* WB1 = (const float*)d_in[13];
    const float* gB1 = (const float*)d_in[14];
    const float* bB1 = (const float*)d_in[15];
    const float* WB2 = (const float*)d_in[16];
    const float* gB2 = (const float*)d_in[17];
    const float* bB2 = (const float*)d_in[18];

    float *pt1, *pt2, *pPgA, *pPcA, *pPgB, *pPcB;
    float *pMaxA, *pMinA, *pMaxB, *pMinB;
    float *pScale, *pShift;
    uint32_t *pl0p, *pW2p, *pWA1g, *pWA1d, *pWA2p, *pWB1g, *pWB1d, *pWB2p;
    cudaGetSymbolAddress((void**)&pt1,  d_t1);
    cudaGetSymbolAddress((void**)&pt2,  d_t2);
    cudaGetSymbolAddress((void**)&pPgA, d_PgA);
    cudaGetSymbolAddress((void**)&pPcA, d_PcA);
    cudaGetSymbolAddress((void**)&pPgB, d_PgB);
    cudaGetSymbolAddress((void**)&pPcB, d_PcB);
    cudaGetSymbolAddress((void**)&pMaxA, d_maxA);
    cudaGetSymbolAddress((void**)&pMinA, d_minA);
    cudaGetSymbolAddress((void**)&pMaxB, d_maxB);
    cudaGetSymbolAddress((void**)&pMinB, d_minB);
    cudaGetSymbolAddress((void**)&pScale, d_scale);
    cudaGetSymbolAddress((void**)&pShift, d_shift);
    cudaGetSymbolAddress((void**)&pl0p,  d_l0p);
    cudaGetSymbolAddress((void**)&pW2p,  d_W2p);
    cudaGetSymbolAddress((void**)&pWA1g, d_WA1g);
    cudaGetSymbolAddress((void**)&pWA1d, d_WA1d);
    cudaGetSymbolAddress((void**)&pWA2p, d_WA2p);
    cudaGetSymbolAddress((void**)&pWB1g, d_WB1g);
    cudaGetSymbolAddress((void**)&pWB1d, d_WB1d);
    cudaGetSymbolAddress((void**)&pWB2p, d_WB2p);

    cudaFuncSetAttribute(k_gemm_mma<0, 0>, cudaFuncAttributeMaxDynamicSharedMemorySize, GSMEM);
    cudaFuncSetAttribute(k_gemm_mma<1, 2>, cudaFuncAttributeMaxDynamicSharedMemorySize, GSMEM);
    cudaFuncSetAttribute(k_gemm_mma<2, 0>, cudaFuncAttributeMaxDynamicSharedMemorySize, GSMEM);
    cudaFuncSetAttribute(k_gemm_mma<2, 1>, cudaFuncAttributeMaxDynamicSharedMemorySize, GSMEM);

    k_init_stats<<<24, 256>>>();

    // pack all weights (inputs only; safe to run first)
    k_pack<<<(256 * 64 + 255) / 256, 256>>>(W2, nullptr, pW2p, 64, 64, 256 * 64);
    k_pack<<<(512 * 256 + 255) / 256, 256>>>(WA1, nullptr, pWA1g, 256, 512, 512 * 256);
    k_pack<<<(512 * 256 + 255) / 256, 256>>>(WA1 + 256, WA1, pWA1d, 256, 512, 512 * 256);
    k_pack<<<(512 * 512 + 255) / 256, 256>>>(WA2, nullptr, pWA2p, 512, 512, 512 * 512);
    k_pack<<<(1024 * 512 + 255) / 256, 256>>>(WB1, nullptr, pWB1g, 512, 1024, 1024 * 512);
    k_pack<<<(1024 * 512 + 255) / 256, 256>>>(WB1 + 512, WB1, pWB1d, 512, 1024, 1024 * 512);
    k_pack<<<(1024 * 1024 + 255) / 256, 256>>>(WB2, nullptr, pWB2p, 1024, 1024, 1024 * 1024);

    // MLP stage 1: t1 + stats0
    k_t1<<<256, 256>>>(xyz, W1);
    k_finalize<<<1, 64>>>(0, 64, 8192.0f, g1, b1);

    // MLP stage 2: t2 = bn_relu(t1) @ W2^T  (+fused stats stage1)
    k_gemm_mma<2, 1><<<dim3(2, 64), 512, GSMEM>>>(
        pt1, nullptr, nullptr, nullptr, pScale + 0 * 1024, pShift + 0 * 1024,
        pW2p, pt2, nullptr, nullptr, 256, 64, 1);
    k_finalize<<<1, 256>>>(1, 256, 8192.0f, g2, b2);

    // kNN
    k_knn<<<32, 256>>>(xyz);

    // local_op A, layer 1 factored (A = bn_relu(t2) on the fly)
    k_gemm_mma<2, 0><<<dim3(4, 64), 512, GSMEM>>>(
        pt2, nullptr, nullptr, nullptr, pScale + 1 * 1024, pShift + 1 * 1024,
        pWA1g, pPgA, nullptr, nullptr, 512, 256, 0);
    k_gemm_mma<2, 0><<<dim3(4, 64), 512, GSMEM>>>(
        pt2, nullptr, nullptr, nullptr, pScale + 1 * 1024, pShift + 1 * 1024,
        pWA1d, pPcA, nullptr, nullptr, 512, 256, 0);
    k_stats_u<<<1024, 256>>>(pPgA, pPcA, 512, 2);
    k_finalize<<<2, 256>>>(2, 512, 65536.0f, gA1, bA1);

    // local_op A, layer 2: fused stats(3) + per-point max/min
    k_gemm_mma<1, 2><<<dim3(4, 512), 512, GSMEM>>>(
        nullptr, nullptr, pPgA, pPcA, pScale + 2 * 1024, pShift + 2 * 1024,
        pWA2p, nullptr, pMaxA, pMinA, 512, 512, 3);
    k_finalize<<<2, 256>>>(3, 512, 65536.0f, gA2, bA2);
    k_l0_final<<<4096, 256>>>();

    // local_op B, layer 1 factored (A = packed l0)
    k_gemm_mma<0, 0><<<dim3(8, 64), 512, GSMEM>>>(
        nullptr, pl0p, nullptr, nullptr, nullptr, nullptr,
        pWB1g, pPgB, nullptr, nullptr, 1024, 512, 0);
    k_gemm_mma<0, 0><<<dim3(8, 64), 512, GSMEM>>>(
        nullptr, pl0p, nullptr, nullptr, nullptr, nullptr,
        pWB1d, pPcB, nullptr, nullptr, 1024, 512, 0);
    k_stats_u<<<1024, 256>>>(pPgB, pPcB, 1024, 4);
    k_finalize<<<4, 256>>>(4, 1024, 65536.0f, gB1, bB1);

    // local_op B, layer 2 (dominant GEMM): fused stats(5) + max/min
    k_gemm_mma<1, 2><<<dim3(8, 512), 512, GSMEM>>>(
        nullptr, nullptr, pPgB, pPcB, pScale + 4 * 1024, pShift + 4 * 1024,
        pWB2p, nullptr, pMaxB, pMinB, 1024, 1024, 5);
    k_finalize<<<4, 256>>>(5, 1024, 65536.0f, gB2, bB2);

    // final: bn_relu(select(max/min)) + transpose to (B, C, N)
    k_out_final<<<dim3(32, 32, 8), dim3(32, 8)>>>((float*)d_out);
}